// round 1
// baseline (speedup 1.0000x reference)
#include <cuda_runtime.h>
#include <math.h>

#define BB 16
#define HH 256
#define WW 256
#define CC 64
#define M2K 12
#define NKY 24
#define FCH 128

// ---------------- device-global scratch (no allocations allowed) ----------------
__device__ float  g_hA[(size_t)BB*CC*HH*WW];                 // 268 MB
__device__ float  g_hB[(size_t)BB*CC*HH*WW];                 // 268 MB
__device__ float2 g_xw[(size_t)BB*CC*HH*M2K];                // fwd W-DFT result
__device__ float2 g_xf[(size_t)BB*CC*NKY*M2K];               // fwd modes
__device__ float2 g_yf[(size_t)BB*CC*NKY*M2K];               // mixed modes
__device__ float2 g_g [(size_t)BB*CC*HH*M2K];                // inv-H result
__device__ float2 g_wt[(size_t)4*NKY*M2K*CC*CC];             // transposed spectral weights
__device__ float2 g_tw[256];                                 // e^{2*pi*i*m/256}

// ---------------- twiddle table ----------------
__global__ void k_tw() {
    int m = threadIdx.x;
    double s, c;
    sincospi((double)m / 128.0, &s, &c);   // angle = 2*pi*m/256
    g_tw[m] = make_float2((float)c, (float)s);
}

// ---------------- spectral weight transpose: [l][p][i][o][ky][kx] -> [l][kyi][kx][i][o]
__global__ void k_wt(const float* __restrict__ scw) {
    size_t idx = (size_t)blockIdx.x * 256 + threadIdx.x;
    if (idx >= (size_t)4*2*CC*CC*144) return;
    size_t t = idx;
    int kx = t % 12; t /= 12;
    int ky = t % 12; t /= 12;
    int o  = t % CC; t /= CC;
    int i  = t % CC; t /= CC;
    int p  = t % 2;  t /= 2;
    int l  = (int)t;
    float re = scw[idx*2], im = scw[idx*2+1];
    int kyi = (p == 0) ? ky : (12 + ky);
    size_t dst = ((((size_t)l*NKY + kyi)*12 + kx)*CC + i)*CC + o;
    g_wt[dst] = make_float2(re, im);
}

// ---------------- lift: h[b,c,y,x] = x[b,y,x]*fc0_w[c] + fc0_b[c] ----------------
__global__ void k_lift(const float* __restrict__ x, const float* __restrict__ w,
                       const float* __restrict__ b) {
    size_t idx = (size_t)blockIdx.x * 256 + threadIdx.x;   // (b,c,y,x), x fastest
    int xx = idx & 255;
    int y  = (idx >> 8) & 255;
    int c  = (idx >> 16) & 63;
    int bb = (int)(idx >> 22);
    float xv = x[((size_t)bb*256 + y)*256 + xx];
    g_hA[idx] = xv * w[c] + b[c];
}

// ---------------- forward W-DFT: Xw[b,c,y,kx] = sum_x h * e^{-2pi i kx x/256}, kx<12
__global__ void k_fwd_w(int l) {
    const float* hin = (l & 1) ? g_hB : g_hA;
    __shared__ float2 tw[256];
    for (int t = threadIdx.x; t < 256; t += 256) tw[t] = g_tw[t];
    __syncthreads();
    int warp = threadIdx.x >> 5, lane = threadIdx.x & 31;
    size_t row = (size_t)blockIdx.x * 8 + warp;            // over B*C*H rows
    const float* src = hin + row * 256;
    float v[8];
#pragma unroll
    for (int j = 0; j < 8; j++) v[j] = src[j*32 + lane];
#pragma unroll
    for (int kx = 0; kx < 12; kx++) {
        float sr = 0.f, si = 0.f;
#pragma unroll
        for (int j = 0; j < 8; j++) {
            float2 w = tw[(kx*(j*32 + lane)) & 255];
            sr += v[j] * w.x;
            si -= v[j] * w.y;
        }
#pragma unroll
        for (int off = 16; off; off >>= 1) {
            sr += __shfl_xor_sync(0xffffffffu, sr, off);
            si += __shfl_xor_sync(0xffffffffu, si, off);
        }
        if (lane == 0) g_xw[row*12 + kx] = make_float2(sr, si);
    }
}

// ---------------- forward H-DFT: XF[b,c,kyi,kx] = sum_y Xw * e^{-2pi i ky y/256}
__global__ void k_fwd_h() {
    __shared__ float2 s[3072];       // Xw[b,c] tile: 256 y x 12 kx
    __shared__ float2 tw[256];
    int bc = blockIdx.x;
    for (int t = threadIdx.x; t < 256;  t += 256) tw[t] = g_tw[t];
    for (int t = threadIdx.x; t < 3072; t += 256) s[t] = g_xw[(size_t)bc*3072 + t];
    __syncthreads();
    for (int out = threadIdx.x; out < 288; out += 256) {
        int kyi = out / 12, kx = out % 12;
        int ky  = (kyi < 12) ? kyi : (kyi + 232);   // 244 + (kyi-12), mod-256 phase
        float ar = 0.f, ai = 0.f;
        for (int y = 0; y < 256; y++) {
            float2 a = s[y*12 + kx];
            float2 w = tw[(ky*y) & 255];
            // a * e^{-i theta}
            ar += a.x*w.x + a.y*w.y;
            ai += a.y*w.x - a.x*w.y;
        }
        g_xf[(size_t)bc*288 + out] = make_float2(ar, ai);
    }
}

// ---------------- mode mixing: Y[b,o,cell] = sum_i XF[b,i,cell] * W[l,cell,i,o]
__global__ void k_mix(int l) {
    __shared__ float2 sxf[4][64];
    int b = blockIdx.x / 72, grp = blockIdx.x % 72;
    int cell0 = grp * 4;
    {
        int c = threadIdx.x >> 6, i = threadIdx.x & 63;
        sxf[c][i] = g_xf[((size_t)b*CC + i)*288 + cell0 + c];
    }
    __syncthreads();
    int cc = threadIdx.x >> 6, o = threadIdx.x & 63;
    int cell = cell0 + cc;
    int kyi = cell / 12, kx = cell % 12;
    const float2* wp = g_wt + (((size_t)l*NKY + kyi)*12 + kx)*4096 + o;
    float ar = 0.f, ai = 0.f;
#pragma unroll 8
    for (int i = 0; i < 64; i++) {
        float2 a = sxf[cc][i];
        float2 w = wp[(size_t)i * 64];
        ar += a.x*w.x - a.y*w.y;
        ai += a.x*w.y + a.y*w.x;
    }
    g_yf[((size_t)b*CC + o)*288 + cell] = make_float2(ar, ai);
}

// ---------------- inverse H: G[b,o,y,kx] = sum_kyi Y * e^{+2pi i ky y/256}
__global__ void k_inv_h() {
    __shared__ float2 sy[288];
    __shared__ float2 tw[256];
    int bo = blockIdx.x;
    for (int t = threadIdx.x; t < 256; t += 256) tw[t] = g_tw[t];
    for (int t = threadIdx.x; t < 288; t += 256) sy[t] = g_yf[(size_t)bo*288 + t];
    __syncthreads();
    int y = threadIdx.x;
    float2 acc[12];
#pragma unroll
    for (int kx = 0; kx < 12; kx++) acc[kx] = make_float2(0.f, 0.f);
    for (int kyi = 0; kyi < 24; kyi++) {
        int ky = (kyi < 12) ? kyi : (kyi + 232);
        float2 w = tw[(ky*y) & 255];
#pragma unroll
        for (int kx = 0; kx < 12; kx++) {
            float2 a = sy[kyi*12 + kx];
            acc[kx].x += a.x*w.x - a.y*w.y;
            acc[kx].y += a.x*w.y + a.y*w.x;
        }
    }
#pragma unroll
    for (int kx = 0; kx < 12; kx++)
        g_g[((size_t)bo*256 + y)*12 + kx] = acc[kx];
}

// ---------------- fused: inverse W + pointwise conv + bias + gelu ----------------
__global__ void k_combine(const float* __restrict__ pw_w, const float* __restrict__ pw_b,
                          int l) {
    const float* hin  = (l & 1) ? g_hB : g_hA;
    float*       hout = (l & 1) ? g_hA : g_hB;
    __shared__ float  hs[64][64];     // [i][xx]
    __shared__ float  ws[64][64];     // [o][i]
    __shared__ float2 gb[64][12];     // [o][kx]
    __shared__ float2 tw[256];
    __shared__ float  bs[64];
    int xt = blockIdx.x & 3;
    int y  = (blockIdx.x >> 2) & 255;
    int b  = blockIdx.x >> 10;
    int x0 = xt << 6;
    for (int t = threadIdx.x; t < 256; t += 256) tw[t] = g_tw[t];
    for (int t = threadIdx.x; t < 4096; t += 256) {
        hs[t>>6][t&63] = hin[(((size_t)b*64 + (t>>6))*256 + y)*256 + x0 + (t&63)];
        ws[t>>6][t&63] = pw_w[l*4096 + t];
    }
    for (int t = threadIdx.x; t < 768; t += 256)
        gb[t/12][t%12] = g_g[(((size_t)b*64 + t/12)*256 + y)*12 + (t%12)];
    if (threadIdx.x < 64) bs[threadIdx.x] = pw_b[l*64 + threadIdx.x];
    __syncthreads();

    int xx = threadIdx.x & 63;
    int og = threadIdx.x >> 6;       // 0..3, each owns 16 output channels
    int x  = x0 + xx;
    float acc[16];
#pragma unroll
    for (int k = 0; k < 16; k++) acc[k] = 0.f;
    for (int i = 0; i < 64; i++) {
        float hv = hs[i][xx];
#pragma unroll
        for (int k = 0; k < 16; k++) acc[k] += hv * ws[og*16 + k][i];
    }
#pragma unroll
    for (int k = 0; k < 16; k++) {
        int o = og*16 + k;
        float sp = gb[o][0].x;                       // DC bin: Im discarded by irfft
#pragma unroll
        for (int kx = 1; kx < 12; kx++) {
            float2 w = tw[(kx*x) & 255];
            sp += 2.f * (gb[o][kx].x*w.x - gb[o][kx].y*w.y);
        }
        float v = acc[k] + bs[o] + sp * (1.f/65536.f);
        if (l < 3) v = 0.5f * v * (1.f + erff(v * 0.70710678118654752f));
        hout[(((size_t)b*64 + o)*256 + y)*256 + x] = v;
    }
}

// ---------------- final: fc1 + gelu + fc2 ----------------
__global__ void k_final(const float* __restrict__ w1, const float* __restrict__ b1,
                        const float* __restrict__ w2, const float* __restrict__ b2,
                        float* __restrict__ out) {
    __shared__ float sw1[8192];   // [c][d]
    __shared__ float sb1[128];
    __shared__ float sw2[128];
    int y = blockIdx.x & 255, b = blockIdx.x >> 8;
    for (int t = threadIdx.x; t < 8192; t += 256) sw1[t] = w1[t];
    if (threadIdx.x < 128) { sb1[threadIdx.x] = b1[threadIdx.x]; sw2[threadIdx.x] = w2[threadIdx.x]; }
    __syncthreads();
    int x = threadIdx.x;
    float hv[64];
#pragma unroll
    for (int c = 0; c < 64; c++)
        hv[c] = g_hA[(((size_t)b*64 + c)*256 + y)*256 + x];
    float acc = b2[0];
    for (int d = 0; d < 128; d++) {
        float s = sb1[d];
#pragma unroll
        for (int c = 0; c < 64; c++) s += hv[c] * sw1[c*128 + d];
        s = 0.5f * s * (1.f + erff(s * 0.70710678118654752f));
        acc += s * sw2[d];
    }
    out[((size_t)b*256 + y)*256 + x] = acc;
}

// ---------------- launcher ----------------
extern "C" void kernel_launch(void* const* d_in, const int* in_sizes, int n_in,
                              void* d_out, int out_size) {
    const float* x     = (const float*)d_in[0];
    const float* fc0_w = (const float*)d_in[1];
    const float* fc0_b = (const float*)d_in[2];
    const float* sc_w  = (const float*)d_in[3];
    const float* pw_w  = (const float*)d_in[4];
    const float* pw_b  = (const float*)d_in[5];
    const float* fc1_w = (const float*)d_in[6];
    const float* fc1_b = (const float*)d_in[7];
    const float* fc2_w = (const float*)d_in[8];
    const float* fc2_b = (const float*)d_in[9];
    float* out = (float*)d_out;

    k_tw<<<1, 256>>>();
    k_wt<<<18432, 256>>>(sc_w);
    k_lift<<<262144, 256>>>(x, fc0_w, fc0_b);
    for (int l = 0; l < 4; l++) {
        k_fwd_w<<<32768, 256>>>(l);          // B*C*H/8 rows
        k_fwd_h<<<1024, 256>>>();            // B*C blocks
        k_mix<<<1152, 256>>>(l);             // B * 72 groups of 4 mode-cells
        k_inv_h<<<1024, 256>>>();            // B*C blocks (output channels)
        k_combine<<<16384, 256>>>(pw_w, pw_b, l);   // B*H*4 x-tiles
    }
    k_final<<<4096, 256>>>(fc1_w, fc1_b, fc2_w, fc2_b, out);
}

// round 2
// speedup vs baseline: 1.6273x; 1.6273x over previous
#include <cuda_runtime.h>
#include <math.h>

#define BB 16
#define HH 256
#define WW 256
#define CC 64
#define M2K 12
#define NKY 24
#define FCH 128

// ---------------- device-global scratch ----------------
__device__ float  g_hA[(size_t)BB*CC*HH*WW];
__device__ float  g_hB[(size_t)BB*CC*HH*WW];
__device__ float2 g_xw[(size_t)BB*CC*HH*M2K];
__device__ float2 g_xf[(size_t)BB*CC*NKY*M2K];
__device__ float2 g_yf[(size_t)BB*CC*NKY*M2K];
__device__ float2 g_g [(size_t)BB*CC*HH*M2K];
__device__ float2 g_wt[(size_t)4*NKY*M2K*CC*CC];
__device__ float  g_pwt[(size_t)4*CC*CC];       // pointwise weights transposed [l][i][o]
__device__ float2 g_tw[256];

// ---------------- f32x2 packed helpers ----------------
__device__ __forceinline__ unsigned long long pack2(float a, float b) {
    unsigned long long r;
    asm("mov.b64 %0, {%1, %2};" : "=l"(r) : "f"(a), "f"(b));
    return r;
}
__device__ __forceinline__ unsigned long long bcast2(float a) {
    unsigned long long r;
    asm("mov.b64 %0, {%1, %1};" : "=l"(r) : "f"(a));
    return r;
}
__device__ __forceinline__ unsigned long long fma2(unsigned long long a,
                                                   unsigned long long b,
                                                   unsigned long long c) {
    unsigned long long d;
    asm("fma.rn.f32x2 %0, %1, %2, %3;" : "=l"(d) : "l"(a), "l"(b), "l"(c));
    return d;
}
__device__ __forceinline__ float2 unpack2(unsigned long long a) {
    float2 f;
    asm("mov.b64 {%0, %1}, %2;" : "=f"(f.x), "=f"(f.y) : "l"(a));
    return f;
}

// ---------------- twiddle table ----------------
__global__ void k_tw() {
    int m = threadIdx.x;
    double s, c;
    sincospi((double)m / 128.0, &s, &c);
    g_tw[m] = make_float2((float)c, (float)s);
}

// ---------------- spectral weight transpose ----------------
__global__ void k_wt(const float* __restrict__ scw) {
    size_t idx = (size_t)blockIdx.x * 256 + threadIdx.x;
    if (idx >= (size_t)4*2*CC*CC*144) return;
    size_t t = idx;
    int kx = t % 12; t /= 12;
    int ky = t % 12; t /= 12;
    int o  = t % CC; t /= CC;
    int i  = t % CC; t /= CC;
    int p  = t % 2;  t /= 2;
    int l  = (int)t;
    float re = scw[idx*2], im = scw[idx*2+1];
    int kyi = (p == 0) ? ky : (12 + ky);
    size_t dst = ((((size_t)l*NKY + kyi)*12 + kx)*CC + i)*CC + o;
    g_wt[dst] = make_float2(re, im);
}

// ---------------- pointwise weight transpose: [l][o][i] -> [l][i][o] ----------------
__global__ void k_pwt(const float* __restrict__ pw) {
    int idx = blockIdx.x * 256 + threadIdx.x;   // 16384
    int l = idx >> 12, o = (idx >> 6) & 63, i = idx & 63;
    g_pwt[l*4096 + i*64 + o] = pw[idx];
}

// ---------------- lift (float4) ----------------
__global__ void k_lift(const float* __restrict__ x, const float* __restrict__ w,
                       const float* __restrict__ b) {
    size_t i4 = (size_t)blockIdx.x * 256 + threadIdx.x;   // float4 index
    int x4 = i4 & 63;
    int y  = (i4 >> 6) & 255;
    int c  = (i4 >> 14) & 63;
    int bb = (int)(i4 >> 20);
    float4 xv = ((const float4*)x)[((size_t)bb*256 + y)*64 + x4];
    float wc = w[c], bc = b[c];
    float4 o;
    o.x = xv.x*wc + bc; o.y = xv.y*wc + bc; o.z = xv.z*wc + bc; o.w = xv.w*wc + bc;
    ((float4*)g_hA)[i4] = o;
}

// ---------------- forward W-DFT via 8pt DFT + lane-phase recurrence ----------------
__global__ void k_fwd_w(int l) {
    const float* hin = (l & 1) ? g_hB : g_hA;
    int warp = threadIdx.x >> 5, lane = threadIdx.x & 31;
    size_t row = (size_t)blockIdx.x * 8 + warp;
    const float* src = hin + row * 256;
    float v[8];
#pragma unroll
    for (int j = 0; j < 8; j++) v[j] = src[lane + j*32];

    // 8-point DFT over j (stride-32 samples): S[m] = sum_j v_j e^{-2pi i m j/8}
    const float cst = 0.70710678118654752f;
    float a0 = v[0]+v[4], b0 = v[0]-v[4];
    float a2 = v[2]+v[6], b2 = v[2]-v[6];
    float a1 = v[1]+v[5], b1 = v[1]-v[5];
    float a3 = v[3]+v[7], b3 = v[3]-v[7];
    float G0 = a0+a2, G2 = a0-a2;
    float H0 = a1+a3, H2 = a1-a3;
    float d1 = cst*(b1-b3), d2 = cst*(b1+b3);
    float2 S[8];
    S[0] = make_float2(G0+H0, 0.f);
    S[4] = make_float2(G0-H0, 0.f);
    S[2] = make_float2(G2, -H2);
    S[6] = make_float2(G2,  H2);
    S[1] = make_float2(b0 + d1, -b2 - d2);
    S[5] = make_float2(b0 - d1, -b2 + d2);
    S[3] = make_float2(b0 - d1,  b2 - d2);
    S[7] = make_float2(b0 + d1,  b2 + d2);

    // lane phase: step = e^{-2pi i lane/256}
    float sn, cs;
    sincospif((float)lane * (1.f/128.f), &sn, &cs);
    float2 step = make_float2(cs, -sn);
    float2 wl = make_float2(1.f, 0.f);

#pragma unroll
    for (int kx = 0; kx < 12; kx++) {
        float2 Sv = S[kx & 7];
        float xr = Sv.x*wl.x - Sv.y*wl.y;
        float xi = Sv.x*wl.y + Sv.y*wl.x;
#pragma unroll
        for (int off = 16; off; off >>= 1) {
            xr += __shfl_xor_sync(0xffffffffu, xr, off);
            xi += __shfl_xor_sync(0xffffffffu, xi, off);
        }
        if (lane == 0) g_xw[row*12 + kx] = make_float2(xr, xi);
        float nr = wl.x*step.x - wl.y*step.y;
        float ni = wl.x*step.y + wl.y*step.x;
        wl = make_float2(nr, ni);
    }
}

// ---------------- forward H-DFT ----------------
__global__ void k_fwd_h() {
    __shared__ float2 s[3072];
    __shared__ float2 tw[256];
    int bc = blockIdx.x;
    for (int t = threadIdx.x; t < 256;  t += 256) tw[t] = g_tw[t];
    for (int t = threadIdx.x; t < 3072; t += 256) s[t] = g_xw[(size_t)bc*3072 + t];
    __syncthreads();
    for (int out = threadIdx.x; out < 288; out += 256) {
        int kyi = out / 12, kx = out % 12;
        int ky  = (kyi < 12) ? kyi : (kyi + 232);
        float ar = 0.f, ai = 0.f;
        for (int y = 0; y < 256; y++) {
            float2 a = s[y*12 + kx];
            float2 w = tw[(ky*y) & 255];
            ar += a.x*w.x + a.y*w.y;
            ai += a.y*w.x - a.x*w.y;
        }
        g_xf[(size_t)bc*288 + out] = make_float2(ar, ai);
    }
}

// ---------------- mode mixing ----------------
__global__ void k_mix(int l) {
    __shared__ float2 sxf[4][64];
    int b = blockIdx.x / 72, grp = blockIdx.x % 72;
    int cell0 = grp * 4;
    {
        int c = threadIdx.x >> 6, i = threadIdx.x & 63;
        sxf[c][i] = g_xf[((size_t)b*CC + i)*288 + cell0 + c];
    }
    __syncthreads();
    int cc = threadIdx.x >> 6, o = threadIdx.x & 63;
    int cell = cell0 + cc;
    int kyi = cell / 12, kx = cell % 12;
    const float2* wp = g_wt + (((size_t)l*NKY + kyi)*12 + kx)*4096 + o;
    float ar = 0.f, ai = 0.f;
#pragma unroll 8
    for (int i = 0; i < 64; i++) {
        float2 a = sxf[cc][i];
        float2 w = wp[(size_t)i * 64];
        ar += a.x*w.x - a.y*w.y;
        ai += a.x*w.y + a.y*w.x;
    }
    g_yf[((size_t)b*CC + o)*288 + cell] = make_float2(ar, ai);
}

// ---------------- inverse H ----------------
__global__ void k_inv_h() {
    __shared__ float2 sy[288];
    __shared__ float2 tw[256];
    int bo = blockIdx.x;
    for (int t = threadIdx.x; t < 256; t += 256) tw[t] = g_tw[t];
    for (int t = threadIdx.x; t < 288; t += 256) sy[t] = g_yf[(size_t)bo*288 + t];
    __syncthreads();
    int y = threadIdx.x;
    float2 acc[12];
#pragma unroll
    for (int kx = 0; kx < 12; kx++) acc[kx] = make_float2(0.f, 0.f);
    for (int kyi = 0; kyi < 24; kyi++) {
        int ky = (kyi < 12) ? kyi : (kyi + 232);
        float2 w = tw[(ky*y) & 255];
#pragma unroll
        for (int kx = 0; kx < 12; kx++) {
            float2 a = sy[kyi*12 + kx];
            acc[kx].x += a.x*w.x - a.y*w.y;
            acc[kx].y += a.x*w.y + a.y*w.x;
        }
    }
#pragma unroll
    for (int kx = 0; kx < 12; kx++)
        g_g[((size_t)bo*256 + y)*12 + kx] = acc[kx];
}

// ---------------- fused: inverse W + pointwise conv + bias + gelu ----------------
__global__ void __launch_bounds__(256) k_combine(const float* __restrict__ pw_b, int l) {
    const float* hin  = (l & 1) ? g_hB : g_hA;
    float*       hout = (l & 1) ? g_hA : g_hB;
    __shared__ __align__(16) float  hs[64*64];    // [i][x]
    __shared__ __align__(16) float  wst[64*64];   // [i][o]
    __shared__ float2 gb[64*12];                  // [o][kx]
    __shared__ float  bs[64];
    int xt = blockIdx.x & 3;
    int y  = (blockIdx.x >> 2) & 255;
    int b  = blockIdx.x >> 10;
    int x0 = xt << 6;
    int tid = threadIdx.x;

    for (int t = tid; t < 1024; t += 256) {
        int i = t >> 4, q = t & 15;
        ((float4*)hs)[t]  = *(const float4*)(hin + ((((size_t)b*64 + i)*256 + y) << 8) + x0 + q*4);
        ((float4*)wst)[t] = ((const float4*)(g_pwt + l*4096))[t];
    }
    for (int t = tid; t < 768; t += 256) {
        int o = t / 12, kx = t % 12;
        gb[t] = g_g[(((size_t)b*64 + o)*256 + y)*12 + kx];
    }
    if (tid < 64) bs[tid] = pw_b[l*64 + tid];
    __syncthreads();

    int tx = tid & 15, to = tid >> 4;   // 16 x-groups (4x each), 16 o-groups (4o each)

    // GEMM part: acc2[x][p] = packed (o=to*4+2p, +2p+1)
    unsigned long long acc2[4][2];
#pragma unroll
    for (int k = 0; k < 4; k++) { acc2[k][0] = 0ull; acc2[k][1] = 0ull; }
#pragma unroll 4
    for (int i = 0; i < 64; i++) {
        float4 h4 = *(const float4*)&hs[i*64 + tx*4];
        ulonglong2 wv = *(const ulonglong2*)&wst[i*64 + to*4];
        unsigned long long h0 = bcast2(h4.x), h1 = bcast2(h4.y),
                           h2 = bcast2(h4.z), h3 = bcast2(h4.w);
        acc2[0][0] = fma2(h0, wv.x, acc2[0][0]); acc2[0][1] = fma2(h0, wv.y, acc2[0][1]);
        acc2[1][0] = fma2(h1, wv.x, acc2[1][0]); acc2[1][1] = fma2(h1, wv.y, acc2[1][1]);
        acc2[2][0] = fma2(h2, wv.x, acc2[2][0]); acc2[2][1] = fma2(h2, wv.y, acc2[2][1]);
        acc2[3][0] = fma2(h3, wv.x, acc2[3][0]); acc2[3][1] = fma2(h3, wv.y, acc2[3][1]);
    }
    float acc[4][4];   // [o][x]
#pragma unroll
    for (int k = 0; k < 4; k++) {
        float2 f0 = unpack2(acc2[k][0]);
        float2 f1 = unpack2(acc2[k][1]);
        acc[0][k] = f0.x; acc[1][k] = f0.y; acc[2][k] = f1.x; acc[3][k] = f1.y;
    }

    // spectral reconstruction along x (irfft last step), twiddle recurrence per x
    float sp[4][4];
#pragma unroll
    for (int o = 0; o < 4; o++)
#pragma unroll
        for (int k = 0; k < 4; k++) sp[o][k] = gb[(to*4 + o)*12].x;   // DC (Im dropped)
    float2 stp[4], wr[4];
#pragma unroll
    for (int k = 0; k < 4; k++) { stp[k] = g_tw[x0 + tx*4 + k]; wr[k] = stp[k]; }
#pragma unroll
    for (int kx = 1; kx < 12; kx++) {
        float2 g[4];
#pragma unroll
        for (int o = 0; o < 4; o++) g[o] = gb[(to*4 + o)*12 + kx];
#pragma unroll
        for (int o = 0; o < 4; o++)
#pragma unroll
            for (int k = 0; k < 4; k++)
                sp[o][k] += 2.f * (g[o].x*wr[k].x - g[o].y*wr[k].y);
#pragma unroll
        for (int k = 0; k < 4; k++) {
            float nr = wr[k].x*stp[k].x - wr[k].y*stp[k].y;
            float ni = wr[k].x*stp[k].y + wr[k].y*stp[k].x;
            wr[k] = make_float2(nr, ni);
        }
    }

    // epilogue: bias + scale + gelu + store
#pragma unroll
    for (int o = 0; o < 4; o++) {
        int oo = to*4 + o;
        float bias = bs[oo];
        float4 st;
        float* stp4 = &st.x;
#pragma unroll
        for (int k = 0; k < 4; k++) {
            float v = acc[o][k] + bias + sp[o][k] * (1.f/65536.f);
            if (l < 3) v = 0.5f * v * (1.f + erff(v * 0.70710678118654752f));
            stp4[k] = v;
        }
        *(float4*)(hout + ((((size_t)b*64 + oo)*256 + y) << 8) + x0 + tx*4) = st;
    }
}

// ---------------- final: fc1 + gelu + fc2 (f32x2) ----------------
__global__ void __launch_bounds__(256) k_final(const float* __restrict__ w1,
                        const float* __restrict__ b1,
                        const float* __restrict__ w2, const float* __restrict__ b2,
                        float* __restrict__ out) {
    __shared__ __align__(16) float w1t[128*64];   // [d][c]
    __shared__ float sb1[128];
    __shared__ float sw2[128];
    int y = blockIdx.x & 255, b = blockIdx.x >> 8;
    for (int t = threadIdx.x; t < 8192; t += 256) {
        int c = t >> 7, d = t & 127;
        w1t[d*64 + c] = w1[t];
    }
    if (threadIdx.x < 128) { sb1[threadIdx.x] = b1[threadIdx.x]; sw2[threadIdx.x] = w2[threadIdx.x]; }
    __syncthreads();
    int x = threadIdx.x;
    unsigned long long hv2[32];
#pragma unroll
    for (int p = 0; p < 32; p++) {
        float h0 = g_hA[(((size_t)b*64 + 2*p    )*256 + y)*256 + x];
        float h1 = g_hA[(((size_t)b*64 + 2*p + 1)*256 + y)*256 + x];
        hv2[p] = pack2(h0, h1);
    }
    float acc = b2[0];
    for (int d = 0; d < 128; d++) {
        const ulonglong2* wr = (const ulonglong2*)&w1t[d*64];
        unsigned long long a0 = 0ull, a1 = 0ull, a2 = 0ull, a3 = 0ull;
#pragma unroll
        for (int q = 0; q < 8; q++) {
            ulonglong2 wA = wr[2*q], wB = wr[2*q + 1];
            a0 = fma2(hv2[4*q    ], wA.x, a0);
            a1 = fma2(hv2[4*q + 1], wA.y, a1);
            a2 = fma2(hv2[4*q + 2], wB.x, a2);
            a3 = fma2(hv2[4*q + 3], wB.y, a3);
        }
        float2 f0 = unpack2(a0), f1 = unpack2(a1), f2 = unpack2(a2), f3 = unpack2(a3);
        float s = ((f0.x + f0.y) + (f1.x + f1.y)) + ((f2.x + f2.y) + (f3.x + f3.y)) + sb1[d];
        s = 0.5f * s * (1.f + erff(s * 0.70710678118654752f));
        acc += s * sw2[d];
    }
    out[((size_t)b*256 + y)*256 + x] = acc;
}

// ---------------- launcher ----------------
extern "C" void kernel_launch(void* const* d_in, const int* in_sizes, int n_in,
                              void* d_out, int out_size) {
    const float* x     = (const float*)d_in[0];
    const float* fc0_w = (const float*)d_in[1];
    const float* fc0_b = (const float*)d_in[2];
    const float* sc_w  = (const float*)d_in[3];
    const float* pw_w  = (const float*)d_in[4];
    const float* pw_b  = (const float*)d_in[5];
    const float* fc1_w = (const float*)d_in[6];
    const float* fc1_b = (const float*)d_in[7];
    const float* fc2_w = (const float*)d_in[8];
    const float* fc2_b = (const float*)d_in[9];
    float* out = (float*)d_out;

    k_tw<<<1, 256>>>();
    k_wt<<<18432, 256>>>(sc_w);
    k_pwt<<<64, 256>>>(pw_w);
    k_lift<<<65536, 256>>>(x, fc0_w, fc0_b);
    for (int l = 0; l < 4; l++) {
        k_fwd_w<<<32768, 256>>>(l);
        k_fwd_h<<<1024, 256>>>();
        k_mix<<<1152, 256>>>(l);
        k_inv_h<<<1024, 256>>>();
        k_combine<<<16384, 256>>>(pw_b, l);
    }
    k_final<<<4096, 256>>>(fc1_w, fc1_b, fc2_w, fc2_b, out);
}

// round 4
// speedup vs baseline: 1.8929x; 1.1632x over previous
#include <cuda_runtime.h>
#include <cuda_bf16.h>
#include <math.h>

#define BB 16
#define HH 256
#define WW 256
#define CC 64
#define M2K 12
#define NKY 24
#define FCH 128

// ---------------- device-global scratch ----------------
__device__ float  g_hA[(size_t)BB*CC*HH*WW];
__device__ float  g_hB[(size_t)BB*CC*HH*WW];
__device__ float2 g_xw[(size_t)BB*CC*HH*M2K];
__device__ float2 g_xf[(size_t)BB*CC*NKY*M2K];
__device__ float2 g_yf[(size_t)BB*CC*NKY*M2K];
__device__ float2 g_g [(size_t)BB*CC*HH*M2K];
__device__ float2 g_wt[(size_t)4*NKY*M2K*CC*CC];
__device__ float2 g_tw[256];
__device__ unsigned g_twc[256];   // split-packed cos(2pi m/256)
__device__ unsigned g_tws[256];   // split-packed sin(2pi m/256)

// ---------------- packed f32x2 helpers (k_final) ----------------
__device__ __forceinline__ unsigned long long pack2(float a, float b) {
    unsigned long long r;
    asm("mov.b64 %0, {%1, %2};" : "=l"(r) : "f"(a), "f"(b));
    return r;
}
__device__ __forceinline__ unsigned long long fma2(unsigned long long a,
                                                   unsigned long long b,
                                                   unsigned long long c) {
    unsigned long long d;
    asm("fma.rn.f32x2 %0, %1, %2, %3;" : "=l"(d) : "l"(a), "l"(b), "l"(c));
    return d;
}
__device__ __forceinline__ float2 unpack2(unsigned long long a) {
    float2 f;
    asm("mov.b64 {%0, %1}, %2;" : "=f"(f.x), "=f"(f.y) : "l"(a));
    return f;
}

// ---------------- bf16 split-pack helpers ----------------
// packed uint32: low 16 = bf16 primary p = bf16(a); high 16 = bf16 residual r = bf16(a - p)
__device__ __forceinline__ unsigned split2(float a) {
    __nv_bfloat16 p = __float2bfloat16_rn(a);
    float pf = __bfloat162float(p);
    __nv_bfloat16 r = __float2bfloat16_rn(a - pf);
    return ((unsigned)__bfloat16_as_ushort(r) << 16) | (unsigned)__bfloat16_as_ushort(p);
}
__device__ __forceinline__ unsigned prmt(unsigned a, unsigned b, unsigned s) {
    unsigned d;
    asm("prmt.b32 %0, %1, %2, %3;" : "=r"(d) : "r"(a), "r"(b), "r"(s));
    return d;
}
__device__ __forceinline__ unsigned mulbf2(unsigned a, unsigned b) {
    unsigned d;
    asm("mul.rn.bf16x2 %0, %1, %2;" : "=r"(d) : "r"(a), "r"(b));
    return d;
}
__device__ __forceinline__ unsigned packbf2(float lo, float hi) {
    unsigned l = (unsigned)__bfloat16_as_ushort(__float2bfloat16_rn(lo));
    unsigned h = (unsigned)__bfloat16_as_ushort(__float2bfloat16_rn(hi));
    return (h << 16) | l;
}
// bf16 mma m16n8k8: A 2 regs (rows g, g+8; k pair 2t4,2t4+1), B 1 reg (k pair, col g)
__device__ __forceinline__ void mma_bf16(float d[4], unsigned a0, unsigned a1, unsigned b0) {
    asm volatile("mma.sync.aligned.m16n8k8.row.col.f32.bf16.bf16.f32 "
        "{%0,%1,%2,%3}, {%4,%5}, {%6}, {%0,%1,%2,%3};"
        : "+f"(d[0]), "+f"(d[1]), "+f"(d[2]), "+f"(d[3])
        : "r"(a0), "r"(a1), "r"(b0));
}

// ---------------- twiddle tables ----------------
__global__ void k_tw() {
    int m = threadIdx.x;
    double s, c;
    sincospi((double)m / 128.0, &s, &c);
    g_tw[m]  = make_float2((float)c, (float)s);
    g_twc[m] = split2((float)c);
    g_tws[m] = split2((float)s);
}

// ---------------- spectral weight transpose ----------------
__global__ void k_wt(const float* __restrict__ scw) {
    size_t idx = (size_t)blockIdx.x * 256 + threadIdx.x;
    if (idx >= (size_t)4*2*CC*CC*144) return;
    size_t t = idx;
    int kx = t % 12; t /= 12;
    int ky = t % 12; t /= 12;
    int o  = t % CC; t /= CC;
    int i  = t % CC; t /= CC;
    int p  = t % 2;  t /= 2;
    int l  = (int)t;
    float re = scw[idx*2], im = scw[idx*2+1];
    int kyi = (p == 0) ? ky : (12 + ky);
    size_t dst = ((((size_t)l*NKY + kyi)*12 + kx)*CC + i)*CC + o;
    g_wt[dst] = make_float2(re, im);
}

// ---------------- lift (float4) ----------------
__global__ void k_lift(const float* __restrict__ x, const float* __restrict__ w,
                       const float* __restrict__ b) {
    size_t i4 = (size_t)blockIdx.x * 256 + threadIdx.x;
    int x4 = i4 & 63;
    int y  = (i4 >> 6) & 255;
    int c  = (i4 >> 14) & 63;
    int bb = (int)(i4 >> 20);
    float4 xv = ((const float4*)x)[((size_t)bb*256 + y)*64 + x4];
    float wc = w[c], bc = b[c];
    float4 o;
    o.x = xv.x*wc + bc; o.y = xv.y*wc + bc; o.z = xv.z*wc + bc; o.w = xv.w*wc + bc;
    ((float4*)g_hA)[i4] = o;
}

// ---------------- forward W-DFT via 8pt DFT + lane-phase recurrence ----------------
__global__ void k_fwd_w(int l) {
    const float* hin = (l & 1) ? g_hB : g_hA;
    int warp = threadIdx.x >> 5, lane = threadIdx.x & 31;
    size_t row = (size_t)blockIdx.x * 8 + warp;
    const float* src = hin + row * 256;
    float v[8];
#pragma unroll
    for (int j = 0; j < 8; j++) v[j] = src[lane + j*32];

    const float cst = 0.70710678118654752f;
    float a0 = v[0]+v[4], b0 = v[0]-v[4];
    float a2 = v[2]+v[6], b2 = v[2]-v[6];
    float a1 = v[1]+v[5], b1 = v[1]-v[5];
    float a3 = v[3]+v[7], b3 = v[3]-v[7];
    float G0 = a0+a2, G2 = a0-a2;
    float H0 = a1+a3, H2 = a1-a3;
    float d1 = cst*(b1-b3), d2 = cst*(b1+b3);
    float2 S[8];
    S[0] = make_float2(G0+H0, 0.f);
    S[4] = make_float2(G0-H0, 0.f);
    S[2] = make_float2(G2, -H2);
    S[6] = make_float2(G2,  H2);
    S[1] = make_float2(b0 + d1, -b2 - d2);
    S[5] = make_float2(b0 - d1, -b2 + d2);
    S[3] = make_float2(b0 - d1,  b2 - d2);
    S[7] = make_float2(b0 + d1,  b2 + d2);

    float sn, cs;
    sincospif((float)lane * (1.f/128.f), &sn, &cs);
    float2 step = make_float2(cs, -sn);
    float2 wl = make_float2(1.f, 0.f);

#pragma unroll
    for (int kx = 0; kx < 12; kx++) {
        float2 Sv = S[kx & 7];
        float xr = Sv.x*wl.x - Sv.y*wl.y;
        float xi = Sv.x*wl.y + Sv.y*wl.x;
#pragma unroll
        for (int off = 16; off; off >>= 1) {
            xr += __shfl_xor_sync(0xffffffffu, xr, off);
            xi += __shfl_xor_sync(0xffffffffu, xi, off);
        }
        if (lane == 0) g_xw[row*12 + kx] = make_float2(xr, xi);
        float nr = wl.x*step.x - wl.y*step.y;
        float ni = wl.x*step.y + wl.y*step.x;
        wl = make_float2(nr, ni);
    }
}

// ---------------- forward H-DFT ----------------
__global__ void k_fwd_h() {
    __shared__ float2 s[3072];
    __shared__ float2 tw[256];
    int bc = blockIdx.x;
    for (int t = threadIdx.x; t < 256;  t += 256) tw[t] = g_tw[t];
    for (int t = threadIdx.x; t < 3072; t += 256) s[t] = g_xw[(size_t)bc*3072 + t];
    __syncthreads();
    for (int out = threadIdx.x; out < 288; out += 256) {
        int kyi = out / 12, kx = out % 12;
        int ky  = (kyi < 12) ? kyi : (kyi + 232);
        float ar = 0.f, ai = 0.f;
        for (int y = 0; y < 256; y++) {
            float2 a = s[y*12 + kx];
            float2 w = tw[(ky*y) & 255];
            ar += a.x*w.x + a.y*w.y;
            ai += a.y*w.x - a.x*w.y;
        }
        g_xf[(size_t)bc*288 + out] = make_float2(ar, ai);
    }
}

// ---------------- mode mixing ----------------
__global__ void k_mix(int l) {
    __shared__ float2 sxf[4][64];
    int b = blockIdx.x / 72, grp = blockIdx.x % 72;
    int cell0 = grp * 4;
    {
        int c = threadIdx.x >> 6, i = threadIdx.x & 63;
        sxf[c][i] = g_xf[((size_t)b*CC + i)*288 + cell0 + c];
    }
    __syncthreads();
    int cc = threadIdx.x >> 6, o = threadIdx.x & 63;
    int cell = cell0 + cc;
    int kyi = cell / 12, kx = cell % 12;
    const float2* wp = g_wt + (((size_t)l*NKY + kyi)*12 + kx)*4096 + o;
    float ar = 0.f, ai = 0.f;
#pragma unroll 8
    for (int i = 0; i < 64; i++) {
        float2 a = sxf[cc][i];
        float2 w = wp[(size_t)i * 64];
        ar += a.x*w.x - a.y*w.y;
        ai += a.x*w.y + a.y*w.x;
    }
    g_yf[((size_t)b*CC + o)*288 + cell] = make_float2(ar, ai);
}

// ---------------- inverse H ----------------
__global__ void k_inv_h() {
    __shared__ float2 sy[288];
    __shared__ float2 tw[256];
    int bo = blockIdx.x;
    for (int t = threadIdx.x; t < 256; t += 256) tw[t] = g_tw[t];
    for (int t = threadIdx.x; t < 288; t += 256) sy[t] = g_yf[(size_t)bo*288 + t];
    __syncthreads();
    int y = threadIdx.x;
    float2 acc[12];
#pragma unroll
    for (int kx = 0; kx < 12; kx++) acc[kx] = make_float2(0.f, 0.f);
    for (int kyi = 0; kyi < 24; kyi++) {
        int ky = (kyi < 12) ? kyi : (kyi + 232);
        float2 w = tw[(ky*y) & 255];
#pragma unroll
        for (int kx = 0; kx < 12; kx++) {
            float2 a = sy[kyi*12 + kx];
            acc[kx].x += a.x*w.x - a.y*w.y;
            acc[kx].y += a.x*w.y + a.y*w.x;
        }
    }
#pragma unroll
    for (int kx = 0; kx < 12; kx++)
        g_g[((size_t)bo*256 + y)*12 + kx] = acc[kx];
}

// ---------------- fused combine: bf16x3 residual-split tensor GEMM ----------------
// out[o][x] = sum_{k<64} W[o][k] h[k][x] + sum_j Gr[o][j](a_j cos) + Gi[o][j](-a_j sin)
// K_ext = 88 = 11 tiles of 8. All operands split-packed (bf16 primary|residual).
#define KP 88
#define XP 68
__global__ void __launch_bounds__(256) k_combine(const float* __restrict__ pw_w,
                                                 const float* __restrict__ pw_b, int l) {
    const float* hin  = (l & 1) ? g_hB : g_hA;
    float*       hout = (l & 1) ? g_hA : g_hB;
    __shared__ __align__(16) unsigned sA[64*KP];   // [o][k] split-packed
    __shared__ __align__(16) unsigned sB[64*XP];   // [k<64][x] split-packed; reused as fp32 stage
    __shared__ unsigned s_twc[256];
    __shared__ unsigned s_tws[256];
    __shared__ float  sbias[64];

    int xq = blockIdx.x & 3;
    int y  = (blockIdx.x >> 2) & 255;
    int b  = blockIdx.x >> 10;
    int x0 = xq << 6;
    int tid = threadIdx.x;

    // sB: h tile split-packed
#pragma unroll
    for (int it = 0; it < 4; it++) {
        int t = it*256 + tid;
        int i = t >> 4, q = t & 15;
        float4 v = *(const float4*)(hin + ((((size_t)b*64 + i)*256 + y) << 8) + x0 + q*4);
        uint4 u;
        u.x = split2(v.x); u.y = split2(v.y); u.z = split2(v.z); u.w = split2(v.w);
        *(uint4*)&sB[i*XP + q*4] = u;
    }
    // sA: pointwise weights split-packed
#pragma unroll
    for (int it = 0; it < 16; it++) {
        int t = it*256 + tid;
        int o = t >> 6, k = t & 63;
        sA[o*KP + k] = split2(pw_w[l*4096 + t]);
    }
    // sA: spectral columns (Gr at 64+j, Gi at 76+j)
#pragma unroll
    for (int it = 0; it < 3; it++) {
        int t = it*256 + tid;
        if (t < 768) {
            int o = t / 12, j = t % 12;
            float2 gv = g_g[(((size_t)b*64 + o)*256 + y)*12 + j];
            sA[o*KP + 64 + j] = split2(gv.x);
            sA[o*KP + 76 + j] = split2(gv.y);
        }
    }
    s_twc[tid & 255] = g_twc[tid & 255];
    s_tws[tid & 255] = g_tws[tid & 255];
    if (tid < 64) sbias[tid] = pw_b[l*64 + tid];
    __syncthreads();

    int wid = tid >> 5, lane = tid & 31;
    int mt = wid & 3, nh = wid >> 2;
    int g = lane >> 2, t4 = lane & 3;

    float d[4][4];
#pragma unroll
    for (int nt = 0; nt < 4; nt++)
#pragma unroll
        for (int r = 0; r < 4; r++) d[nt][r] = 0.f;

    const float A1 = 1.f/65536.f, A2 = 2.f/65536.f;
#pragma unroll
    for (int kt = 0; kt < 11; kt++) {
        // A fragment: rows mt*16+g, +8; k pair kt*8 + 2t4, +1
        uint2 wA0 = *(const uint2*)&sA[(mt*16 + g    )*KP + kt*8 + 2*t4];
        uint2 wA1 = *(const uint2*)&sA[(mt*16 + g + 8)*KP + kt*8 + 2*t4];
        unsigned ap0 = prmt(wA0.x, wA0.y, 0x5410u), ar0 = prmt(wA0.x, wA0.y, 0x7632u);
        unsigned ap1 = prmt(wA1.x, wA1.y, 0x5410u), ar1 = prmt(wA1.x, wA1.y, 0x7632u);

        // per-thread spectral row config (kt >= 8)
        int er0 = (kt - 8)*8 + 2*t4;        // valid when kt>=8
        bool cosp = er0 < 12;
        const unsigned* tab = cosp ? s_twc : s_tws;
        int j0 = cosp ? er0 : er0 - 12;
        int j1 = j0 + 1;
        unsigned alpha = 0;
        if (kt >= 8) {
            float al0 = cosp ? ((er0 == 0) ? A1 : A2) : -A2;
            float al1 = cosp ? A2 : -A2;
            alpha = packbf2(al0, al1);
        }

#pragma unroll
        for (int nt = 0; nt < 4; nt++) {
            int xl = nh*32 + nt*8 + g;
            unsigned bp, br;
            if (kt < 8) {
                unsigned w0 = sB[(kt*8 + 2*t4    )*XP + xl];
                unsigned w1 = sB[(kt*8 + 2*t4 + 1)*XP + xl];
                bp = prmt(w0, w1, 0x5410u);
                br = prmt(w0, w1, 0x7632u);
            } else {
                int xg = x0 + xl;
                unsigned w0 = tab[(j0*xg) & 255];
                unsigned w1 = tab[(j1*xg) & 255];
                bp = mulbf2(prmt(w0, w1, 0x5410u), alpha);
                br = mulbf2(prmt(w0, w1, 0x7632u), alpha);
            }
            mma_bf16(d[nt], ap0, ap1, bp);   // Ap * Bp
            mma_bf16(d[nt], ap0, ap1, br);   // Ap * Br
            mma_bf16(d[nt], ar0, ar1, bp);   // Ar * Bp
        }
    }

    // stage D to smem (reuse sB as fp32, stride XP)
    __syncthreads();
    float* sD = (float*)sB;
#pragma unroll
    for (int nt = 0; nt < 4; nt++) {
        int xl = nh*32 + nt*8 + 2*t4;
        int o0 = mt*16 + g;
        *(float2*)&sD[ o0      * XP + xl] = make_float2(d[nt][0], d[nt][1]);
        *(float2*)&sD[(o0 + 8) * XP + xl] = make_float2(d[nt][2], d[nt][3]);
    }
    __syncthreads();

    // epilogue: bias + gelu + coalesced store
#pragma unroll
    for (int it = 0; it < 4; it++) {
        int o  = it*16 + (tid >> 4);
        int x4 = tid & 15;
        float4 v = *(float4*)&sD[o*XP + x4*4];
        float bias = sbias[o];
        float* vp = &v.x;
#pragma unroll
        for (int k = 0; k < 4; k++) {
            float u = vp[k] + bias;
            if (l < 3) u = 0.5f * u * (1.f + erff(u * 0.70710678118654752f));
            vp[k] = u;
        }
        *(float4*)(hout + ((((size_t)b*64 + o)*256 + y) << 8) + x0 + x4*4) = v;
    }
}

// ---------------- final: fc1 + gelu + fc2 (f32x2) ----------------
__global__ void __launch_bounds__(256) k_final(const float* __restrict__ w1,
                        const float* __restrict__ b1,
                        const float* __restrict__ w2, const float* __restrict__ b2,
                        float* __restrict__ out) {
    __shared__ __align__(16) float w1t[128*64];   // [d][c]
    __shared__ float sb1[128];
    __shared__ float sw2[128];
    int y = blockIdx.x & 255, b = blockIdx.x >> 8;
    for (int t = threadIdx.x; t < 8192; t += 256) {
        int c = t >> 7, d = t & 127;
        w1t[d*64 + c] = w1[t];
    }
    if (threadIdx.x < 128) { sb1[threadIdx.x] = b1[threadIdx.x]; sw2[threadIdx.x] = w2[threadIdx.x]; }
    __syncthreads();
    int x = threadIdx.x;
    unsigned long long hv2[32];
#pragma unroll
    for (int p = 0; p < 32; p++) {
        float h0 = g_hA[(((size_t)b*64 + 2*p    )*256 + y)*256 + x];
        float h1 = g_hA[(((size_t)b*64 + 2*p + 1)*256 + y)*256 + x];
        hv2[p] = pack2(h0, h1);
    }
    float acc = b2[0];
    for (int d = 0; d < 128; d++) {
        const ulonglong2* wr = (const ulonglong2*)&w1t[d*64];
        unsigned long long a0 = 0ull, a1 = 0ull, a2 = 0ull, a3 = 0ull;
#pragma unroll
        for (int q = 0; q < 8; q++) {
            ulonglong2 wA = wr[2*q], wB = wr[2*q + 1];
            a0 = fma2(hv2[4*q    ], wA.x, a0);
            a1 = fma2(hv2[4*q + 1], wA.y, a1);
            a2 = fma2(hv2[4*q + 2], wB.x, a2);
            a3 = fma2(hv2[4*q + 3], wB.y, a3);
        }
        float2 f0 = unpack2(a0), f1 = unpack2(a1), f2 = unpack2(a2), f3 = unpack2(a3);
        float s = ((f0.x + f0.y) + (f1.x + f1.y)) + ((f2.x + f2.y) + (f3.x + f3.y)) + sb1[d];
        s = 0.5f * s * (1.f + erff(s * 0.70710678118654752f));
        acc += s * sw2[d];
    }
    out[((size_t)b*256 + y)*256 + x] = acc;
}

// ---------------- launcher ----------------
extern "C" void kernel_launch(void* const* d_in, const int* in_sizes, int n_in,
                              void* d_out, int out_size) {
    const float* x     = (const float*)d_in[0];
    const float* fc0_w = (const float*)d_in[1];
    const float* fc0_b = (const float*)d_in[2];
    const float* sc_w  = (const float*)d_in[3];
    const float* pw_w  = (const float*)d_in[4];
    const float* pw_b  = (const float*)d_in[5];
    const float* fc1_w = (const float*)d_in[6];
    const float* fc1_b = (const float*)d_in[7];
    const float* fc2_w = (const float*)d_in[8];
    const float* fc2_b = (const float*)d_in[9];
    float* out = (float*)d_out;

    k_tw<<<1, 256>>>();
    k_wt<<<18432, 256>>>(sc_w);
    k_lift<<<65536, 256>>>(x, fc0_w, fc0_b);
    for (int l = 0; l < 4; l++) {
        k_fwd_w<<<32768, 256>>>(l);
        k_fwd_h<<<1024, 256>>>();
        k_mix<<<1152, 256>>>(l);
        k_inv_h<<<1024, 256>>>();
        k_combine<<<16384, 256>>>(pw_w, pw_b, l);
    }
    k_final<<<4096, 256>>>(fc1_w, fc1_b, fc2_w, fc2_b, out);
}

// round 6
// speedup vs baseline: 2.0636x; 1.0902x over previous
#include <cuda_runtime.h>
#include <cuda_bf16.h>
#include <math.h>

#define BB 16
#define HH 256
#define WW 256
#define CC 64
#define M2K 12
#define NKY 24
#define FCH 128

// ---------------- device-global scratch ----------------
__device__ float  g_hA[(size_t)BB*CC*HH*WW];
__device__ float  g_hB[(size_t)BB*CC*HH*WW];
__device__ float2 g_xw[(size_t)BB*CC*HH*M2K];
__device__ float2 g_xf[(size_t)BB*CC*NKY*M2K];
__device__ float2 g_yf[(size_t)BB*CC*NKY*M2K];
__device__ float2 g_g [(size_t)BB*CC*HH*M2K];
__device__ float2 g_wt[(size_t)4*NKY*M2K*CC*CC];
__device__ float2 g_tw[256];
__device__ unsigned g_twc[256];   // split-packed cos(2pi m/256)
__device__ unsigned g_tws[256];   // split-packed sin(2pi m/256)
__device__ unsigned g_E[256*24];  // fwd-W DFT matrix, packed split: col 2j=cos, 2j+1=-sin

// ---------------- packed f32x2 helpers (k_final) ----------------
__device__ __forceinline__ unsigned long long pack2(float a, float b) {
    unsigned long long r;
    asm("mov.b64 %0, {%1, %2};" : "=l"(r) : "f"(a), "f"(b));
    return r;
}
__device__ __forceinline__ unsigned long long fma2(unsigned long long a,
                                                   unsigned long long b,
                                                   unsigned long long c) {
    unsigned long long d;
    asm("fma.rn.f32x2 %0, %1, %2, %3;" : "=l"(d) : "l"(a), "l"(b), "l"(c));
    return d;
}
__device__ __forceinline__ float2 unpack2(unsigned long long a) {
    float2 f;
    asm("mov.b64 {%0, %1}, %2;" : "=f"(f.x), "=f"(f.y) : "l"(a));
    return f;
}

// ---------------- bf16 split-pack helpers ----------------
__device__ __forceinline__ unsigned split2(float a) {
    __nv_bfloat16 p = __float2bfloat16_rn(a);
    float pf = __bfloat162float(p);
    __nv_bfloat16 r = __float2bfloat16_rn(a - pf);
    return ((unsigned)__bfloat16_as_ushort(r) << 16) | (unsigned)__bfloat16_as_ushort(p);
}
__device__ __forceinline__ unsigned prmt(unsigned a, unsigned b, unsigned s) {
    unsigned d;
    asm("prmt.b32 %0, %1, %2, %3;" : "=r"(d) : "r"(a), "r"(b), "r"(s));
    return d;
}
__device__ __forceinline__ unsigned mulbf2(unsigned a, unsigned b) {
    unsigned d;
    asm("mul.rn.bf16x2 %0, %1, %2;" : "=r"(d) : "r"(a), "r"(b));
    return d;
}
__device__ __forceinline__ unsigned packbf2(float lo, float hi) {
    unsigned l = (unsigned)__bfloat16_as_ushort(__float2bfloat16_rn(lo));
    unsigned h = (unsigned)__bfloat16_as_ushort(__float2bfloat16_rn(hi));
    return (h << 16) | l;
}
__device__ __forceinline__ void mma_bf16(float d[4], unsigned a0, unsigned a1, unsigned b0) {
    asm volatile("mma.sync.aligned.m16n8k8.row.col.f32.bf16.bf16.f32 "
        "{%0,%1,%2,%3}, {%4,%5}, {%6}, {%0,%1,%2,%3};"
        : "+f"(d[0]), "+f"(d[1]), "+f"(d[2]), "+f"(d[3])
        : "r"(a0), "r"(a1), "r"(b0));
}

// ---------------- twiddle tables ----------------
__global__ void k_tw() {
    int m = threadIdx.x;
    double s, c;
    sincospi((double)m / 128.0, &s, &c);
    g_tw[m]  = make_float2((float)c, (float)s);
    g_twc[m] = split2((float)c);
    g_tws[m] = split2((float)s);
}

// E[x][2j] = cos(2pi j x/256), E[x][2j+1] = -sin(2pi j x/256), split-packed
__global__ void k_E() {
    int x = threadIdx.x;
#pragma unroll
    for (int j = 0; j < 12; j++) {
        double s, c;
        sincospi((double)((j * x) & 255) / 128.0, &s, &c);
        g_E[x*24 + 2*j    ] = split2((float)c);
        g_E[x*24 + 2*j + 1] = split2(-(float)s);
    }
}

// ---------------- spectral weight transpose ----------------
__global__ void k_wt(const float* __restrict__ scw) {
    size_t idx = (size_t)blockIdx.x * 256 + threadIdx.x;
    if (idx >= (size_t)4*2*CC*CC*144) return;
    size_t t = idx;
    int kx = t % 12; t /= 12;
    int ky = t % 12; t /= 12;
    int o  = t % CC; t /= CC;
    int i  = t % CC; t /= CC;
    int p  = t % 2;  t /= 2;
    int l  = (int)t;
    float re = scw[idx*2], im = scw[idx*2+1];
    int kyi = (p == 0) ? ky : (12 + ky);
    size_t dst = ((((size_t)l*NKY + kyi)*12 + kx)*CC + i)*CC + o;
    g_wt[dst] = make_float2(re, im);
}

// ---------------- lift (float4) ----------------
__global__ void k_lift(const float* __restrict__ x, const float* __restrict__ w,
                       const float* __restrict__ b) {
    size_t i4 = (size_t)blockIdx.x * 256 + threadIdx.x;
    int x4 = i4 & 63;
    int y  = (i4 >> 6) & 255;
    int c  = (i4 >> 14) & 63;
    int bb = (int)(i4 >> 20);
    float4 xv = ((const float4*)x)[((size_t)bb*256 + y)*64 + x4];
    float wc = w[c], bc = b[c];
    float4 o;
    o.x = xv.x*wc + bc; o.y = xv.y*wc + bc; o.z = xv.z*wc + bc; o.w = xv.w*wc + bc;
    ((float4*)g_hA)[i4] = o;
}

// ---------------- forward W-DFT as bf16x3 tensor GEMM ----------------
// Xw[row, :] = h[row, 0:256] x E[256 x 24]   (cols interleaved re/im)
#define EST 28
#define AST 33
__global__ void __launch_bounds__(256) k_fwd_w(int l) {
    const float* hin = (l & 1) ? g_hB : g_hA;
    __shared__ __align__(16) unsigned sE[256*EST];   // 28672 B
    __shared__ __align__(16) unsigned sA[128*AST];   // 16896 B
    int tid = threadIdx.x;
    size_t row0 = (size_t)blockIdx.x * 128;

    for (int t = tid; t < 256*24; t += 256)
        sE[(t/24)*EST + (t%24)] = g_E[t];

    int wid = tid >> 5, lane = tid & 31, g = lane >> 2, t4 = lane & 3;
    float d[3][4];
#pragma unroll
    for (int nt = 0; nt < 3; nt++)
#pragma unroll
        for (int r = 0; r < 4; r++) d[nt][r] = 0.f;

#pragma unroll 1
    for (int xc = 0; xc < 8; xc++) {
        __syncthreads();
#pragma unroll
        for (int it = 0; it < 4; it++) {
            int t = it*256 + tid;
            int r = t >> 3, q = t & 7;
            float4 v = *(const float4*)(hin + (row0 + r)*256 + xc*32 + q*4);
            sA[r*AST + q*4 + 0] = split2(v.x);
            sA[r*AST + q*4 + 1] = split2(v.y);
            sA[r*AST + q*4 + 2] = split2(v.z);
            sA[r*AST + q*4 + 3] = split2(v.w);
        }
        __syncthreads();
#pragma unroll
        for (int kk = 0; kk < 4; kk++) {
            int ko = kk*8 + 2*t4;
            // scalar 32-bit LDS (odd stride AST=33 -> uint2 would be misaligned)
            unsigned a0x = sA[(wid*16 + g    )*AST + ko];
            unsigned a0y = sA[(wid*16 + g    )*AST + ko + 1];
            unsigned a1x = sA[(wid*16 + g + 8)*AST + ko];
            unsigned a1y = sA[(wid*16 + g + 8)*AST + ko + 1];
            unsigned ap0 = prmt(a0x, a0y, 0x5410u), ar0 = prmt(a0x, a0y, 0x7632u);
            unsigned ap1 = prmt(a1x, a1y, 0x5410u), ar1 = prmt(a1x, a1y, 0x7632u);
            int gx = xc*32 + ko;
#pragma unroll
            for (int nt = 0; nt < 3; nt++) {
                int n = nt*8 + g;
                unsigned w0 = sE[ gx     *EST + n];
                unsigned w1 = sE[(gx + 1)*EST + n];
                unsigned bp = prmt(w0, w1, 0x5410u);
                unsigned br = prmt(w0, w1, 0x7632u);
                mma_bf16(d[nt], ap0, ap1, bp);
                mma_bf16(d[nt], ap0, ap1, br);
                mma_bf16(d[nt], ar0, ar1, bp);
            }
        }
    }
    // C write: thread quad (g,t4), n-tile nt -> kx = nt*4 + t4
#pragma unroll
    for (int nt = 0; nt < 3; nt++) {
        int kx = nt*4 + t4;
        g_xw[(row0 + wid*16 + g    )*12 + kx] = make_float2(d[nt][0], d[nt][1]);
        g_xw[(row0 + wid*16 + g + 8)*12 + kx] = make_float2(d[nt][2], d[nt][3]);
    }
}

// ---------------- forward H-DFT ----------------
__global__ void k_fwd_h() {
    __shared__ float2 s[3072];
    __shared__ float2 tw[256];
    int bc = blockIdx.x;
    for (int t = threadIdx.x; t < 256;  t += 256) tw[t] = g_tw[t];
    for (int t = threadIdx.x; t < 3072; t += 256) s[t] = g_xw[(size_t)bc*3072 + t];
    __syncthreads();
    for (int out = threadIdx.x; out < 288; out += 256) {
        int kyi = out / 12, kx = out % 12;
        int ky  = (kyi < 12) ? kyi : (kyi + 232);
        float ar = 0.f, ai = 0.f;
        for (int y = 0; y < 256; y++) {
            float2 a = s[y*12 + kx];
            float2 w = tw[(ky*y) & 255];
            ar += a.x*w.x + a.y*w.y;
            ai += a.y*w.x - a.x*w.y;
        }
        g_xf[(size_t)bc*288 + out] = make_float2(ar, ai);
    }
}

// ---------------- mode mixing ----------------
__global__ void k_mix(int l) {
    __shared__ float2 sxf[4][64];
    int b = blockIdx.x / 72, grp = blockIdx.x % 72;
    int cell0 = grp * 4;
    {
        int c = threadIdx.x >> 6, i = threadIdx.x & 63;
        sxf[c][i] = g_xf[((size_t)b*CC + i)*288 + cell0 + c];
    }
    __syncthreads();
    int cc = threadIdx.x >> 6, o = threadIdx.x & 63;
    int cell = cell0 + cc;
    int kyi = cell / 12, kx = cell % 12;
    const float2* wp = g_wt + (((size_t)l*NKY + kyi)*12 + kx)*4096 + o;
    float ar = 0.f, ai = 0.f;
#pragma unroll 8
    for (int i = 0; i < 64; i++) {
        float2 a = sxf[cc][i];
        float2 w = wp[(size_t)i * 64];
        ar += a.x*w.x - a.y*w.y;
        ai += a.x*w.y + a.y*w.x;
    }
    g_yf[((size_t)b*CC + o)*288 + cell] = make_float2(ar, ai);
}

// ---------------- inverse H ----------------
__global__ void k_inv_h() {
    __shared__ float2 sy[288];
    __shared__ float2 tw[256];
    int bo = blockIdx.x;
    for (int t = threadIdx.x; t < 256; t += 256) tw[t] = g_tw[t];
    for (int t = threadIdx.x; t < 288; t += 256) sy[t] = g_yf[(size_t)bo*288 + t];
    __syncthreads();
    int y = threadIdx.x;
    float2 acc[12];
#pragma unroll
    for (int kx = 0; kx < 12; kx++) acc[kx] = make_float2(0.f, 0.f);
    for (int kyi = 0; kyi < 24; kyi++) {
        int ky = (kyi < 12) ? kyi : (kyi + 232);
        float2 w = tw[(ky*y) & 255];
#pragma unroll
        for (int kx = 0; kx < 12; kx++) {
            float2 a = sy[kyi*12 + kx];
            acc[kx].x += a.x*w.x - a.y*w.y;
            acc[kx].y += a.x*w.y + a.y*w.x;
        }
    }
#pragma unroll
    for (int kx = 0; kx < 12; kx++)
        g_g[((size_t)bo*256 + y)*12 + kx] = acc[kx];
}

// ---------------- fused combine: bf16x3 residual-split tensor GEMM ----------------
#define KP 88
#define XP 68
__global__ void __launch_bounds__(256) k_combine(const float* __restrict__ pw_w,
                                                 const float* __restrict__ pw_b, int l) {
    const float* hin  = (l & 1) ? g_hB : g_hA;
    float*       hout = (l & 1) ? g_hA : g_hB;
    __shared__ __align__(16) unsigned sA[64*KP];
    __shared__ __align__(16) unsigned sB[64*XP];
    __shared__ unsigned s_twc[256];
    __shared__ unsigned s_tws[256];
    __shared__ float  sbias[64];

    int xq = blockIdx.x & 3;
    int y  = (blockIdx.x >> 2) & 255;
    int b  = blockIdx.x >> 10;
    int x0 = xq << 6;
    int tid = threadIdx.x;

#pragma unroll
    for (int it = 0; it < 4; it++) {
        int t = it*256 + tid;
        int i = t >> 4, q = t & 15;
        float4 v = *(const float4*)(hin + ((((size_t)b*64 + i)*256 + y) << 8) + x0 + q*4);
        uint4 u;
        u.x = split2(v.x); u.y = split2(v.y); u.z = split2(v.z); u.w = split2(v.w);
        *(uint4*)&sB[i*XP + q*4] = u;
    }
#pragma unroll
    for (int it = 0; it < 16; it++) {
        int t = it*256 + tid;
        int o = t >> 6, k = t & 63;
        sA[o*KP + k] = split2(pw_w[l*4096 + t]);
    }
#pragma unroll
    for (int it = 0; it < 3; it++) {
        int t = it*256 + tid;
        if (t < 768) {
            int o = t / 12, j = t % 12;
            float2 gv = g_g[(((size_t)b*64 + o)*256 + y)*12 + j];
            sA[o*KP + 64 + j] = split2(gv.x);
            sA[o*KP + 76 + j] = split2(gv.y);
        }
    }
    s_twc[tid & 255] = g_twc[tid & 255];
    s_tws[tid & 255] = g_tws[tid & 255];
    if (tid < 64) sbias[tid] = pw_b[l*64 + tid];
    __syncthreads();

    int wid = tid >> 5, lane = tid & 31;
    int mt = wid & 3, nh = wid >> 2;
    int g = lane >> 2, t4 = lane & 3;

    float d[4][4];
#pragma unroll
    for (int nt = 0; nt < 4; nt++)
#pragma unroll
        for (int r = 0; r < 4; r++) d[nt][r] = 0.f;

    const float A1 = 1.f/65536.f, A2 = 2.f/65536.f;
#pragma unroll
    for (int kt = 0; kt < 11; kt++) {
        uint2 wA0 = *(const uint2*)&sA[(mt*16 + g    )*KP + kt*8 + 2*t4];
        uint2 wA1 = *(const uint2*)&sA[(mt*16 + g + 8)*KP + kt*8 + 2*t4];
        unsigned ap0 = prmt(wA0.x, wA0.y, 0x5410u), ar0 = prmt(wA0.x, wA0.y, 0x7632u);
        unsigned ap1 = prmt(wA1.x, wA1.y, 0x5410u), ar1 = prmt(wA1.x, wA1.y, 0x7632u);

        int er0 = (kt - 8)*8 + 2*t4;
        bool cosp = er0 < 12;
        const unsigned* tab = cosp ? s_twc : s_tws;
        int j0 = cosp ? er0 : er0 - 12;
        int j1 = j0 + 1;
        unsigned alpha = 0;
        if (kt >= 8) {
            float al0 = cosp ? ((er0 == 0) ? A1 : A2) : -A2;
            float al1 = cosp ? A2 : -A2;
            alpha = packbf2(al0, al1);
        }

#pragma unroll
        for (int nt = 0; nt < 4; nt++) {
            int xl = nh*32 + nt*8 + g;
            unsigned bp, br;
            if (kt < 8) {
                unsigned w0 = sB[(kt*8 + 2*t4    )*XP + xl];
                unsigned w1 = sB[(kt*8 + 2*t4 + 1)*XP + xl];
                bp = prmt(w0, w1, 0x5410u);
                br = prmt(w0, w1, 0x7632u);
            } else {
                int xg = x0 + xl;
                unsigned w0 = tab[(j0*xg) & 255];
                unsigned w1 = tab[(j1*xg) & 255];
                bp = mulbf2(prmt(w0, w1, 0x5410u), alpha);
                br = mulbf2(prmt(w0, w1, 0x7632u), alpha);
            }
            mma_bf16(d[nt], ap0, ap1, bp);
            mma_bf16(d[nt], ap0, ap1, br);
            mma_bf16(d[nt], ar0, ar1, bp);
        }
    }

    __syncthreads();
    float* sD = (float*)sB;
#pragma unroll
    for (int nt = 0; nt < 4; nt++) {
        int xl = nh*32 + nt*8 + 2*t4;
        int o0 = mt*16 + g;
        *(float2*)&sD[ o0      * XP + xl] = make_float2(d[nt][0], d[nt][1]);
        *(float2*)&sD[(o0 + 8) * XP + xl] = make_float2(d[nt][2], d[nt][3]);
    }
    __syncthreads();

#pragma unroll
    for (int it = 0; it < 4; it++) {
        int o  = it*16 + (tid >> 4);
        int x4 = tid & 15;
        float4 v = *(float4*)&sD[o*XP + x4*4];
        float bias = sbias[o];
        float* vp = &v.x;
#pragma unroll
        for (int k = 0; k < 4; k++) {
            float u = vp[k] + bias;
            if (l < 3) u = 0.5f * u * (1.f + erff(u * 0.70710678118654752f));
            vp[k] = u;
        }
        *(float4*)(hout + ((((size_t)b*64 + o)*256 + y) << 8) + x0 + x4*4) = v;
    }
}

// ---------------- final: fc1 + gelu + fc2 (f32x2) ----------------
__global__ void __launch_bounds__(256) k_final(const float* __restrict__ w1,
                        const float* __restrict__ b1,
                        const float* __restrict__ w2, const float* __restrict__ b2,
                        float* __restrict__ out) {
    __shared__ __align__(16) float w1t[128*64];
    __shared__ float sb1[128];
    __shared__ float sw2[128];
    int y = blockIdx.x & 255, b = blockIdx.x >> 8;
    for (int t = threadIdx.x; t < 8192; t += 256) {
        int c = t >> 7, d = t & 127;
        w1t[d*64 + c] = w1[t];
    }
    if (threadIdx.x < 128) { sb1[threadIdx.x] = b1[threadIdx.x]; sw2[threadIdx.x] = w2[threadIdx.x]; }
    __syncthreads();
    int x = threadIdx.x;
    unsigned long long hv2[32];
#pragma unroll
    for (int p = 0; p < 32; p++) {
        float h0 = g_hA[(((size_t)b*64 + 2*p    )*256 + y)*256 + x];
        float h1 = g_hA[(((size_t)b*64 + 2*p + 1)*256 + y)*256 + x];
        hv2[p] = pack2(h0, h1);
    }
    float acc = b2[0];
    for (int d = 0; d < 128; d++) {
        const ulonglong2* wr = (const ulonglong2*)&w1t[d*64];
        unsigned long long a0 = 0ull, a1 = 0ull, a2 = 0ull, a3 = 0ull;
#pragma unroll
        for (int q = 0; q < 8; q++) {
            ulonglong2 wA = wr[2*q], wB = wr[2*q + 1];
            a0 = fma2(hv2[4*q    ], wA.x, a0);
            a1 = fma2(hv2[4*q + 1], wA.y, a1);
            a2 = fma2(hv2[4*q + 2], wB.x, a2);
            a3 = fma2(hv2[4*q + 3], wB.y, a3);
        }
        float2 f0 = unpack2(a0), f1 = unpack2(a1), f2 = unpack2(a2), f3 = unpack2(a3);
        float s = ((f0.x + f0.y) + (f1.x + f1.y)) + ((f2.x + f2.y) + (f3.x + f3.y)) + sb1[d];
        s = 0.5f * s * (1.f + erff(s * 0.70710678118654752f));
        acc += s * sw2[d];
    }
    out[((size_t)b*256 + y)*256 + x] = acc;
}

// ---------------- launcher ----------------
extern "C" void kernel_launch(void* const* d_in, const int* in_sizes, int n_in,
                              void* d_out, int out_size) {
    const float* x     = (const float*)d_in[0];
    const float* fc0_w = (const float*)d_in[1];
    const float* fc0_b = (const float*)d_in[2];
    const float* sc_w  = (const float*)d_in[3];
    const float* pw_w  = (const float*)d_in[4];
    const float* pw_b  = (const float*)d_in[5];
    const float* fc1_w = (const float*)d_in[6];
    const float* fc1_b = (const float*)d_in[7];
    const float* fc2_w = (const float*)d_in[8];
    const float* fc2_b = (const float*)d_in[9];
    float* out = (float*)d_out;

    k_tw<<<1, 256>>>();
    k_E<<<1, 256>>>();
    k_wt<<<18432, 256>>>(sc_w);
    k_lift<<<65536, 256>>>(x, fc0_w, fc0_b);
    for (int l = 0; l < 4; l++) {
        k_fwd_w<<<2048, 256>>>(l);
        k_fwd_h<<<1024, 256>>>();
        k_mix<<<1152, 256>>>(l);
        k_inv_h<<<1024, 256>>>();
        k_combine<<<16384, 256>>>(pw_w, pw_b, l);
    }
    k_final<<<4096, 256>>>(fc1_w, fc1_b, fc2_w, fc2_b, out);
}

// round 7
// speedup vs baseline: 2.0803x; 1.0081x over previous
#include <cuda_runtime.h>
#include <cuda_bf16.h>
#include <math.h>

#define BB 16
#define HH 256
#define WW 256
#define CC 64
#define M2K 12
#define NKY 24
#define FCH 128

// ---------------- device-global scratch ----------------
__device__ float    g_hA [(size_t)BB*CC*HH*WW];   // fp32 h (final layer only)
__device__ unsigned g_hPA[(size_t)BB*CC*HH*WW];   // split-packed h ping
__device__ unsigned g_hPB[(size_t)BB*CC*HH*WW];   // split-packed h pong
__device__ float2 g_xw[(size_t)BB*CC*HH*M2K];
__device__ float2 g_xf[(size_t)BB*CC*NKY*M2K];
__device__ float2 g_yf[(size_t)BB*CC*NKY*M2K];
__device__ float2 g_g [(size_t)BB*CC*HH*M2K];
__device__ float2 g_wt[(size_t)4*NKY*M2K*CC*CC];
__device__ float2 g_tw[256];
__device__ unsigned g_twc[256];    // split-packed cos
__device__ unsigned g_tws[256];    // split-packed sin
__device__ unsigned g_E[256*24];   // fwd-W DFT matrix split-packed
__device__ unsigned g_pwp[4*CC*CC];// split-packed pointwise weights [l][o][i]

// ---------------- packed f32x2 helpers ----------------
__device__ __forceinline__ unsigned long long pack2(float a, float b) {
    unsigned long long r;
    asm("mov.b64 %0, {%1, %2};" : "=l"(r) : "f"(a), "f"(b));
    return r;
}
__device__ __forceinline__ unsigned long long fma2(unsigned long long a,
                                                   unsigned long long b,
                                                   unsigned long long c) {
    unsigned long long d;
    asm("fma.rn.f32x2 %0, %1, %2, %3;" : "=l"(d) : "l"(a), "l"(b), "l"(c));
    return d;
}
__device__ __forceinline__ float2 unpack2(unsigned long long a) {
    float2 f;
    asm("mov.b64 {%0, %1}, %2;" : "=f"(f.x), "=f"(f.y) : "l"(a));
    return f;
}

// ---------------- bf16 split-pack helpers ----------------
__device__ __forceinline__ unsigned split2(float a) {
    __nv_bfloat16 p = __float2bfloat16_rn(a);
    float pf = __bfloat162float(p);
    __nv_bfloat16 r = __float2bfloat16_rn(a - pf);
    return ((unsigned)__bfloat16_as_ushort(r) << 16) | (unsigned)__bfloat16_as_ushort(p);
}
__device__ __forceinline__ unsigned prmt(unsigned a, unsigned b, unsigned s) {
    unsigned d;
    asm("prmt.b32 %0, %1, %2, %3;" : "=r"(d) : "r"(a), "r"(b), "r"(s));
    return d;
}
__device__ __forceinline__ unsigned mulbf2(unsigned a, unsigned b) {
    unsigned d;
    asm("mul.rn.bf16x2 %0, %1, %2;" : "=r"(d) : "r"(a), "r"(b));
    return d;
}
__device__ __forceinline__ unsigned packbf2(float lo, float hi) {
    unsigned l = (unsigned)__bfloat16_as_ushort(__float2bfloat16_rn(lo));
    unsigned h = (unsigned)__bfloat16_as_ushort(__float2bfloat16_rn(hi));
    return (h << 16) | l;
}
__device__ __forceinline__ void mma_bf16(float d[4], unsigned a0, unsigned a1, unsigned b0) {
    asm volatile("mma.sync.aligned.m16n8k8.row.col.f32.bf16.bf16.f32 "
        "{%0,%1,%2,%3}, {%4,%5}, {%6}, {%0,%1,%2,%3};"
        : "+f"(d[0]), "+f"(d[1]), "+f"(d[2]), "+f"(d[3])
        : "r"(a0), "r"(a1), "r"(b0));
}

// ---------------- twiddle tables ----------------
__global__ void k_tw() {
    int m = threadIdx.x;
    double s, c;
    sincospi((double)m / 128.0, &s, &c);
    g_tw[m]  = make_float2((float)c, (float)s);
    g_twc[m] = split2((float)c);
    g_tws[m] = split2((float)s);
}

__global__ void k_E() {
    int x = threadIdx.x;
#pragma unroll
    for (int j = 0; j < 12; j++) {
        double s, c;
        sincospi((double)((j * x) & 255) / 128.0, &s, &c);
        g_E[x*24 + 2*j    ] = split2((float)c);
        g_E[x*24 + 2*j + 1] = split2(-(float)s);
    }
}

// pack pointwise weights
__global__ void k_pws(const float* __restrict__ pw) {
    int idx = blockIdx.x * 256 + threadIdx.x;   // 16384
    g_pwp[idx] = split2(pw[idx]);
}

// ---------------- spectral weight transpose ----------------
__global__ void k_wt(const float* __restrict__ scw) {
    size_t idx = (size_t)blockIdx.x * 256 + threadIdx.x;
    if (idx >= (size_t)4*2*CC*CC*144) return;
    size_t t = idx;
    int kx = t % 12; t /= 12;
    int ky = t % 12; t /= 12;
    int o  = t % CC; t /= CC;
    int i  = t % CC; t /= CC;
    int p  = t % 2;  t /= 2;
    int l  = (int)t;
    float re = scw[idx*2], im = scw[idx*2+1];
    int kyi = (p == 0) ? ky : (12 + ky);
    size_t dst = ((((size_t)l*NKY + kyi)*12 + kx)*CC + i)*CC + o;
    g_wt[dst] = make_float2(re, im);
}

// ---------------- lift: writes split-packed h ----------------
__global__ void k_lift(const float* __restrict__ x, const float* __restrict__ w,
                       const float* __restrict__ b) {
    size_t i4 = (size_t)blockIdx.x * 256 + threadIdx.x;
    int x4 = i4 & 63;
    int y  = (i4 >> 6) & 255;
    int c  = (i4 >> 14) & 63;
    int bb = (int)(i4 >> 20);
    float4 xv = ((const float4*)x)[((size_t)bb*256 + y)*64 + x4];
    float wc = w[c], bc = b[c];
    uint4 o;
    o.x = split2(xv.x*wc + bc); o.y = split2(xv.y*wc + bc);
    o.z = split2(xv.z*wc + bc); o.w = split2(xv.w*wc + bc);
    ((uint4*)g_hPA)[i4] = o;
}

// ---------------- forward W-DFT as bf16x3 tensor GEMM (packed input) ----------------
#define EST 28
#define AST 33
__global__ void __launch_bounds__(256) k_fwd_w(int l) {
    const unsigned* hin = (l & 1) ? g_hPB : g_hPA;
    __shared__ __align__(16) unsigned sE[256*EST];
    __shared__ __align__(16) unsigned sA[128*AST];
    int tid = threadIdx.x;
    size_t row0 = (size_t)blockIdx.x * 128;

    for (int t = tid; t < 256*24; t += 256)
        sE[(t/24)*EST + (t%24)] = g_E[t];

    int wid = tid >> 5, lane = tid & 31, g = lane >> 2, t4 = lane & 3;
    float d[3][4];
#pragma unroll
    for (int nt = 0; nt < 3; nt++)
#pragma unroll
        for (int r = 0; r < 4; r++) d[nt][r] = 0.f;

#pragma unroll 1
    for (int xc = 0; xc < 8; xc++) {
        __syncthreads();
#pragma unroll
        for (int it = 0; it < 4; it++) {
            int t = it*256 + tid;
            int r = t >> 3, q = t & 7;
            uint4 v = *(const uint4*)(hin + (row0 + r)*256 + xc*32 + q*4);
            sA[r*AST + q*4 + 0] = v.x;
            sA[r*AST + q*4 + 1] = v.y;
            sA[r*AST + q*4 + 2] = v.z;
            sA[r*AST + q*4 + 3] = v.w;
        }
        __syncthreads();
#pragma unroll
        for (int kk = 0; kk < 4; kk++) {
            int ko = kk*8 + 2*t4;
            unsigned a0x = sA[(wid*16 + g    )*AST + ko];
            unsigned a0y = sA[(wid*16 + g    )*AST + ko + 1];
            unsigned a1x = sA[(wid*16 + g + 8)*AST + ko];
            unsigned a1y = sA[(wid*16 + g + 8)*AST + ko + 1];
            unsigned ap0 = prmt(a0x, a0y, 0x5410u), ar0 = prmt(a0x, a0y, 0x7632u);
            unsigned ap1 = prmt(a1x, a1y, 0x5410u), ar1 = prmt(a1x, a1y, 0x7632u);
            int gx = xc*32 + ko;
#pragma unroll
            for (int nt = 0; nt < 3; nt++) {
                int n = nt*8 + g;
                unsigned w0 = sE[ gx     *EST + n];
                unsigned w1 = sE[(gx + 1)*EST + n];
                unsigned bp = prmt(w0, w1, 0x5410u);
                unsigned br = prmt(w0, w1, 0x7632u);
                mma_bf16(d[nt], ap0, ap1, bp);
                mma_bf16(d[nt], ap0, ap1, br);
                mma_bf16(d[nt], ar0, ar1, bp);
            }
        }
    }
#pragma unroll
    for (int nt = 0; nt < 3; nt++) {
        int kx = nt*4 + t4;
        g_xw[(row0 + wid*16 + g    )*12 + kx] = make_float2(d[nt][0], d[nt][1]);
        g_xw[(row0 + wid*16 + g + 8)*12 + kx] = make_float2(d[nt][2], d[nt][3]);
    }
}

// ---------------- forward H-DFT ----------------
__global__ void k_fwd_h() {
    __shared__ float2 s[3072];
    __shared__ float2 tw[256];
    int bc = blockIdx.x;
    for (int t = threadIdx.x; t < 256;  t += 256) tw[t] = g_tw[t];
    for (int t = threadIdx.x; t < 3072; t += 256) s[t] = g_xw[(size_t)bc*3072 + t];
    __syncthreads();
    for (int out = threadIdx.x; out < 288; out += 256) {
        int kyi = out / 12, kx = out % 12;
        int ky  = (kyi < 12) ? kyi : (kyi + 232);
        float ar = 0.f, ai = 0.f;
        for (int y = 0; y < 256; y++) {
            float2 a = s[y*12 + kx];
            float2 w = tw[(ky*y) & 255];
            ar += a.x*w.x + a.y*w.y;
            ai += a.y*w.x - a.x*w.y;
        }
        g_xf[(size_t)bc*288 + out] = make_float2(ar, ai);
    }
}

// ---------------- mode mixing ----------------
__global__ void k_mix(int l) {
    __shared__ float2 sxf[4][64];
    int b = blockIdx.x / 72, grp = blockIdx.x % 72;
    int cell0 = grp * 4;
    {
        int c = threadIdx.x >> 6, i = threadIdx.x & 63;
        sxf[c][i] = g_xf[((size_t)b*CC + i)*288 + cell0 + c];
    }
    __syncthreads();
    int cc = threadIdx.x >> 6, o = threadIdx.x & 63;
    int cell = cell0 + cc;
    int kyi = cell / 12, kx = cell % 12;
    const float2* wp = g_wt + (((size_t)l*NKY + kyi)*12 + kx)*4096 + o;
    float ar = 0.f, ai = 0.f;
#pragma unroll 8
    for (int i = 0; i < 64; i++) {
        float2 a = sxf[cc][i];
        float2 w = wp[(size_t)i * 64];
        ar += a.x*w.x - a.y*w.y;
        ai += a.x*w.y + a.y*w.x;
    }
    g_yf[((size_t)b*CC + o)*288 + cell] = make_float2(ar, ai);
}

// ---------------- inverse H ----------------
__global__ void k_inv_h() {
    __shared__ float2 sy[288];
    __shared__ float2 tw[256];
    int bo = blockIdx.x;
    for (int t = threadIdx.x; t < 256; t += 256) tw[t] = g_tw[t];
    for (int t = threadIdx.x; t < 288; t += 256) sy[t] = g_yf[(size_t)bo*288 + t];
    __syncthreads();
    int y = threadIdx.x;
    float2 acc[12];
#pragma unroll
    for (int kx = 0; kx < 12; kx++) acc[kx] = make_float2(0.f, 0.f);
    for (int kyi = 0; kyi < 24; kyi++) {
        int ky = (kyi < 12) ? kyi : (kyi + 232);
        float2 w = tw[(ky*y) & 255];
#pragma unroll
        for (int kx = 0; kx < 12; kx++) {
            float2 a = sy[kyi*12 + kx];
            acc[kx].x += a.x*w.x - a.y*w.y;
            acc[kx].y += a.x*w.y + a.y*w.x;
        }
    }
#pragma unroll
    for (int kx = 0; kx < 12; kx++)
        g_g[((size_t)bo*256 + y)*12 + kx] = acc[kx];
}

// ---------------- fused combine: per-(b,y) block, 4 x-chunks, packed IO ----------------
#define KP 88
#define XP 68
__global__ void __launch_bounds__(256) k_combine(const float* __restrict__ pw_b, int l) {
    const unsigned* hin = (l & 1) ? g_hPB : g_hPA;
    unsigned* hpout = (l & 1) ? g_hPA : g_hPB;
    __shared__ __align__(16) unsigned sA[64*KP];
    __shared__ __align__(16) unsigned sB[64*XP];
    __shared__ __align__(16) float    sD[64*XP];
    __shared__ unsigned s_twc[256];
    __shared__ unsigned s_tws[256];
    __shared__ float  sbias[64];

    int y = blockIdx.x & 255;
    int b = blockIdx.x >> 8;
    int tid = threadIdx.x;

    // sA: pre-packed weights, coalesced uint4 copy
#pragma unroll
    for (int it = 0; it < 4; it++) {
        int t = it*256 + tid;           // uint4 index 0..1023
        int o = t >> 4, q = t & 15;
        uint4 v = *(const uint4*)(g_pwp + (size_t)l*4096 + o*64 + q*4);
        *(uint4*)&sA[o*KP + q*4] = v;
    }
    // sA: spectral columns (per block, once)
#pragma unroll
    for (int it = 0; it < 3; it++) {
        int t = it*256 + tid;
        if (t < 768) {
            int o = t / 12, j = t % 12;
            float2 gv = g_g[(((size_t)b*64 + o)*256 + y)*12 + j];
            sA[o*KP + 64 + j] = split2(gv.x);
            sA[o*KP + 76 + j] = split2(gv.y);
        }
    }
    s_twc[tid & 255] = g_twc[tid & 255];
    s_tws[tid & 255] = g_tws[tid & 255];
    if (tid < 64) sbias[tid] = pw_b[l*64 + tid];

    int wid = tid >> 5, lane = tid & 31;
    int mt = wid & 3, nh = wid >> 2;
    int g = lane >> 2, t4 = lane & 3;
    const float A1 = 1.f/65536.f, A2 = 2.f/65536.f;

    // prefetch chunk 0
    uint4 pf[4];
#pragma unroll
    for (int it = 0; it < 4; it++) {
        int t = it*256 + tid;
        int i = t >> 4, q = t & 15;
        pf[it] = *(const uint4*)(hin + ((((size_t)b*64 + i)*256 + y) << 8) + q*4);
    }

#pragma unroll 1
    for (int xc = 0; xc < 4; xc++) {
        int x0 = xc << 6;
        // commit prefetched chunk to sB
#pragma unroll
        for (int it = 0; it < 4; it++) {
            int t = it*256 + tid;
            int i = t >> 4, q = t & 15;
            *(uint4*)&sB[i*XP + q*4] = pf[it];
        }
        __syncthreads();
        // prefetch next chunk (overlaps with compute)
        if (xc < 3) {
#pragma unroll
            for (int it = 0; it < 4; it++) {
                int t = it*256 + tid;
                int i = t >> 4, q = t & 15;
                pf[it] = *(const uint4*)(hin + ((((size_t)b*64 + i)*256 + y) << 8) + x0 + 64 + q*4);
            }
        }

        float d[4][4];
#pragma unroll
        for (int nt = 0; nt < 4; nt++)
#pragma unroll
            for (int r = 0; r < 4; r++) d[nt][r] = 0.f;

#pragma unroll
        for (int kt = 0; kt < 11; kt++) {
            uint2 wA0 = *(const uint2*)&sA[(mt*16 + g    )*KP + kt*8 + 2*t4];
            uint2 wA1 = *(const uint2*)&sA[(mt*16 + g + 8)*KP + kt*8 + 2*t4];
            unsigned ap0 = prmt(wA0.x, wA0.y, 0x5410u), ar0 = prmt(wA0.x, wA0.y, 0x7632u);
            unsigned ap1 = prmt(wA1.x, wA1.y, 0x5410u), ar1 = prmt(wA1.x, wA1.y, 0x7632u);

            int er0 = (kt - 8)*8 + 2*t4;
            bool cosp = er0 < 12;
            const unsigned* tab = cosp ? s_twc : s_tws;
            int j0 = cosp ? er0 : er0 - 12;
            int j1 = j0 + 1;
            unsigned alpha = 0;
            if (kt >= 8) {
                float al0 = cosp ? ((er0 == 0) ? A1 : A2) : -A2;
                float al1 = cosp ? A2 : -A2;
                alpha = packbf2(al0, al1);
            }

#pragma unroll
            for (int nt = 0; nt < 4; nt++) {
                int xl = nh*32 + nt*8 + g;
                unsigned bp, br;
                if (kt < 8) {
                    unsigned w0 = sB[(kt*8 + 2*t4    )*XP + xl];
                    unsigned w1 = sB[(kt*8 + 2*t4 + 1)*XP + xl];
                    bp = prmt(w0, w1, 0x5410u);
                    br = prmt(w0, w1, 0x7632u);
                } else {
                    int xg = x0 + xl;
                    unsigned w0 = tab[(j0*xg) & 255];
                    unsigned w1 = tab[(j1*xg) & 255];
                    bp = mulbf2(prmt(w0, w1, 0x5410u), alpha);
                    br = mulbf2(prmt(w0, w1, 0x7632u), alpha);
                }
                mma_bf16(d[nt], ap0, ap1, bp);
                mma_bf16(d[nt], ap0, ap1, br);
                mma_bf16(d[nt], ar0, ar1, bp);
            }
        }

        // stage to sD
#pragma unroll
        for (int nt = 0; nt < 4; nt++) {
            int xl = nh*32 + nt*8 + 2*t4;
            int o0 = mt*16 + g;
            *(float2*)&sD[ o0      * XP + xl] = make_float2(d[nt][0], d[nt][1]);
            *(float2*)&sD[(o0 + 8) * XP + xl] = make_float2(d[nt][2], d[nt][3]);
        }
        __syncthreads();

        // epilogue
#pragma unroll
        for (int it = 0; it < 4; it++) {
            int o  = it*16 + (tid >> 4);
            int x4 = tid & 15;
            float4 v = *(float4*)&sD[o*XP + x4*4];
            float bias = sbias[o];
            size_t base = ((((size_t)b*64 + o)*256 + y) << 8) + x0 + x4*4;
            if (l < 3) {
                float u0 = v.x + bias, u1 = v.y + bias, u2 = v.z + bias, u3 = v.w + bias;
                u0 = 0.5f*u0*(1.f + erff(u0*0.70710678118654752f));
                u1 = 0.5f*u1*(1.f + erff(u1*0.70710678118654752f));
                u2 = 0.5f*u2*(1.f + erff(u2*0.70710678118654752f));
                u3 = 0.5f*u3*(1.f + erff(u3*0.70710678118654752f));
                uint4 up;
                up.x = split2(u0); up.y = split2(u1); up.z = split2(u2); up.w = split2(u3);
                *(uint4*)(hpout + base) = up;
            } else {
                v.x += bias; v.y += bias; v.z += bias; v.w += bias;
                *(float4*)(g_hA + base) = v;
            }
        }
        __syncthreads();
    }
}

// ---------------- final: fc1 + gelu + fc2 (f32x2) ----------------
__global__ void __launch_bounds__(256) k_final(const float* __restrict__ w1,
                        const float* __restrict__ b1,
                        const float* __restrict__ w2, const float* __restrict__ b2,
                        float* __restrict__ out) {
    __shared__ __align__(16) float w1t[128*64];
    __shared__ float sb1[128];
    __shared__ float sw2[128];
    int y = blockIdx.x & 255, b = blockIdx.x >> 8;
    for (int t = threadIdx.x; t < 8192; t += 256) {
        int c = t >> 7, d = t & 127;
        w1t[d*64 + c] = w1[t];
    }
    if (threadIdx.x < 128) { sb1[threadIdx.x] = b1[threadIdx.x]; sw2[threadIdx.x] = w2[threadIdx.x]; }
    __syncthreads();
    int x = threadIdx.x;
    unsigned long long hv2[32];
#pragma unroll
    for (int p = 0; p < 32; p++) {
        float h0 = g_hA[(((size_t)b*64 + 2*p    )*256 + y)*256 + x];
        float h1 = g_hA[(((size_t)b*64 + 2*p + 1)*256 + y)*256 + x];
        hv2[p] = pack2(h0, h1);
    }
    float acc = b2[0];
    for (int d = 0; d < 128; d++) {
        const ulonglong2* wr = (const ulonglong2*)&w1t[d*64];
        unsigned long long a0 = 0ull, a1 = 0ull, a2 = 0ull, a3 = 0ull;
#pragma unroll
        for (int q = 0; q < 8; q++) {
            ulonglong2 wA = wr[2*q], wB = wr[2*q + 1];
            a0 = fma2(hv2[4*q    ], wA.x, a0);
            a1 = fma2(hv2[4*q + 1], wA.y, a1);
            a2 = fma2(hv2[4*q + 2], wB.x, a2);
            a3 = fma2(hv2[4*q + 3], wB.y, a3);
        }
        float2 f0 = unpack2(a0), f1 = unpack2(a1), f2 = unpack2(a2), f3 = unpack2(a3);
        float s = ((f0.x + f0.y) + (f1.x + f1.y)) + ((f2.x + f2.y) + (f3.x + f3.y)) + sb1[d];
        s = 0.5f * s * (1.f + erff(s * 0.70710678118654752f));
        acc += s * sw2[d];
    }
    out[((size_t)b*256 + y)*256 + x] = acc;
}

// ---------------- launcher ----------------
extern "C" void kernel_launch(void* const* d_in, const int* in_sizes, int n_in,
                              void* d_out, int out_size) {
    const float* x     = (const float*)d_in[0];
    const float* fc0_w = (const float*)d_in[1];
    const float* fc0_b = (const float*)d_in[2];
    const float* sc_w  = (const float*)d_in[3];
    const float* pw_w  = (const float*)d_in[4];
    const float* pw_b  = (const float*)d_in[5];
    const float* fc1_w = (const float*)d_in[6];
    const float* fc1_b = (const float*)d_in[7];
    const float* fc2_w = (const float*)d_in[8];
    const float* fc2_b = (const float*)d_in[9];
    float* out = (float*)d_out;

    k_tw<<<1, 256>>>();
    k_E<<<1, 256>>>();
    k_pws<<<64, 256>>>(pw_w);
    k_wt<<<18432, 256>>>(sc_w);
    k_lift<<<65536, 256>>>(x, fc0_w, fc0_b);
    for (int l = 0; l < 4; l++) {
        k_fwd_w<<<2048, 256>>>(l);
        k_fwd_h<<<1024, 256>>>();
        k_mix<<<1152, 256>>>(l);
        k_inv_h<<<1024, 256>>>();
        k_combine<<<4096, 256>>>(pw_b, l);
    }
    k_final<<<4096, 256>>>(fc1_w, fc1_b, fc2_w, fc2_b, out);
}

// round 8
// speedup vs baseline: 2.4475x; 1.1765x over previous
#include <cuda_runtime.h>
#include <cuda_bf16.h>
#include <math.h>

#define BB 16
#define HH 256
#define WW 256
#define CC 64
#define M2K 12
#define NKY 24
#define FCH 128

// ---------------- device-global scratch ----------------
__device__ float    g_hA [(size_t)BB*CC*HH*WW];   // fp32 h (final layer only)
__device__ unsigned g_hPA[(size_t)BB*CC*HH*WW];   // split-packed h ping
__device__ unsigned g_hPB[(size_t)BB*CC*HH*WW];   // split-packed h pong
__device__ float2 g_xw[(size_t)BB*CC*HH*M2K];
__device__ float2 g_xf[(size_t)BB*CC*NKY*M2K];
__device__ float2 g_yf[(size_t)BB*CC*NKY*M2K];
__device__ float2 g_g [(size_t)BB*CC*HH*M2K];
__device__ float2 g_wt[(size_t)4*NKY*M2K*CC*CC];
__device__ float2 g_tw[256];
__device__ unsigned g_twc[256];    // split-packed cos
__device__ unsigned g_tws[256];    // split-packed sin
__device__ unsigned g_E[256*24];   // fwd-W DFT matrix split-packed
__device__ unsigned g_pwp[4*CC*CC];// split-packed pointwise weights [l][o][i]
__device__ unsigned g_w1p[CC*FCH]; // split-packed fc1 weights [c][d]

// ---------------- bf16 split-pack helpers ----------------
__device__ __forceinline__ unsigned split2(float a) {
    __nv_bfloat16 p = __float2bfloat16_rn(a);
    float pf = __bfloat162float(p);
    __nv_bfloat16 r = __float2bfloat16_rn(a - pf);
    return ((unsigned)__bfloat16_as_ushort(r) << 16) | (unsigned)__bfloat16_as_ushort(p);
}
__device__ __forceinline__ unsigned prmt(unsigned a, unsigned b, unsigned s) {
    unsigned d;
    asm("prmt.b32 %0, %1, %2, %3;" : "=r"(d) : "r"(a), "r"(b), "r"(s));
    return d;
}
__device__ __forceinline__ unsigned mulbf2(unsigned a, unsigned b) {
    unsigned d;
    asm("mul.rn.bf16x2 %0, %1, %2;" : "=r"(d) : "r"(a), "r"(b));
    return d;
}
__device__ __forceinline__ unsigned packbf2(float lo, float hi) {
    unsigned l = (unsigned)__bfloat16_as_ushort(__float2bfloat16_rn(lo));
    unsigned h = (unsigned)__bfloat16_as_ushort(__float2bfloat16_rn(hi));
    return (h << 16) | l;
}
__device__ __forceinline__ void mma_bf16(float d[4], unsigned a0, unsigned a1, unsigned b0) {
    asm volatile("mma.sync.aligned.m16n8k8.row.col.f32.bf16.bf16.f32 "
        "{%0,%1,%2,%3}, {%4,%5}, {%6}, {%0,%1,%2,%3};"
        : "+f"(d[0]), "+f"(d[1]), "+f"(d[2]), "+f"(d[3])
        : "r"(a0), "r"(a1), "r"(b0));
}

// ---------------- twiddle tables ----------------
__global__ void k_tw() {
    int m = threadIdx.x;
    double s, c;
    sincospi((double)m / 128.0, &s, &c);
    g_tw[m]  = make_float2((float)c, (float)s);
    g_twc[m] = split2((float)c);
    g_tws[m] = split2((float)s);
}

__global__ void k_E() {
    int x = threadIdx.x;
#pragma unroll
    for (int j = 0; j < 12; j++) {
        double s, c;
        sincospi((double)((j * x) & 255) / 128.0, &s, &c);
        g_E[x*24 + 2*j    ] = split2((float)c);
        g_E[x*24 + 2*j + 1] = split2(-(float)s);
    }
}

// pack pointwise weights
__global__ void k_pws(const float* __restrict__ pw) {
    int idx = blockIdx.x * 256 + threadIdx.x;   // 16384
    g_pwp[idx] = split2(pw[idx]);
}
// pack fc1 weights
__global__ void k_w1p(const float* __restrict__ w1) {
    int idx = blockIdx.x * 256 + threadIdx.x;   // 8192
    g_w1p[idx] = split2(w1[idx]);
}

// ---------------- spectral weight transpose ----------------
__global__ void k_wt(const float* __restrict__ scw) {
    size_t idx = (size_t)blockIdx.x * 256 + threadIdx.x;
    if (idx >= (size_t)4*2*CC*CC*144) return;
    size_t t = idx;
    int kx = t % 12; t /= 12;
    int ky = t % 12; t /= 12;
    int o  = t % CC; t /= CC;
    int i  = t % CC; t /= CC;
    int p  = t % 2;  t /= 2;
    int l  = (int)t;
    float re = scw[idx*2], im = scw[idx*2+1];
    int kyi = (p == 0) ? ky : (12 + ky);
    size_t dst = ((((size_t)l*NKY + kyi)*12 + kx)*CC + i)*CC + o;
    g_wt[dst] = make_float2(re, im);
}

// ---------------- lift: writes split-packed h ----------------
__global__ void k_lift(const float* __restrict__ x, const float* __restrict__ w,
                       const float* __restrict__ b) {
    size_t i4 = (size_t)blockIdx.x * 256 + threadIdx.x;
    int x4 = i4 & 63;
    int y  = (i4 >> 6) & 255;
    int c  = (i4 >> 14) & 63;
    int bb = (int)(i4 >> 20);
    float4 xv = ((const float4*)x)[((size_t)bb*256 + y)*64 + x4];
    float wc = w[c], bc = b[c];
    uint4 o;
    o.x = split2(xv.x*wc + bc); o.y = split2(xv.y*wc + bc);
    o.z = split2(xv.z*wc + bc); o.w = split2(xv.w*wc + bc);
    ((uint4*)g_hPA)[i4] = o;
}

// ---------------- forward W-DFT as bf16x3 tensor GEMM (packed input) ----------------
#define EST 28
#define AST 33
__global__ void __launch_bounds__(256) k_fwd_w(int l) {
    const unsigned* hin = (l & 1) ? g_hPB : g_hPA;
    __shared__ __align__(16) unsigned sE[256*EST];
    __shared__ __align__(16) unsigned sA[128*AST];
    int tid = threadIdx.x;
    size_t row0 = (size_t)blockIdx.x * 128;

    for (int t = tid; t < 256*24; t += 256)
        sE[(t/24)*EST + (t%24)] = g_E[t];

    int wid = tid >> 5, lane = tid & 31, g = lane >> 2, t4 = lane & 3;
    float d[3][4];
#pragma unroll
    for (int nt = 0; nt < 3; nt++)
#pragma unroll
        for (int r = 0; r < 4; r++) d[nt][r] = 0.f;

#pragma unroll 1
    for (int xc = 0; xc < 8; xc++) {
        __syncthreads();
#pragma unroll
        for (int it = 0; it < 4; it++) {
            int t = it*256 + tid;
            int r = t >> 3, q = t & 7;
            uint4 v = *(const uint4*)(hin + (row0 + r)*256 + xc*32 + q*4);
            sA[r*AST + q*4 + 0] = v.x;
            sA[r*AST + q*4 + 1] = v.y;
            sA[r*AST + q*4 + 2] = v.z;
            sA[r*AST + q*4 + 3] = v.w;
        }
        __syncthreads();
#pragma unroll
        for (int kk = 0; kk < 4; kk++) {
            int ko = kk*8 + 2*t4;
            unsigned a0x = sA[(wid*16 + g    )*AST + ko];
            unsigned a0y = sA[(wid*16 + g    )*AST + ko + 1];
            unsigned a1x = sA[(wid*16 + g + 8)*AST + ko];
            unsigned a1y = sA[(wid*16 + g + 8)*AST + ko + 1];
            unsigned ap0 = prmt(a0x, a0y, 0x5410u), ar0 = prmt(a0x, a0y, 0x7632u);
            unsigned ap1 = prmt(a1x, a1y, 0x5410u), ar1 = prmt(a1x, a1y, 0x7632u);
            int gx = xc*32 + ko;
#pragma unroll
            for (int nt = 0; nt < 3; nt++) {
                int n = nt*8 + g;
                unsigned w0 = sE[ gx     *EST + n];
                unsigned w1 = sE[(gx + 1)*EST + n];
                unsigned bp = prmt(w0, w1, 0x5410u);
                unsigned br = prmt(w0, w1, 0x7632u);
                mma_bf16(d[nt], ap0, ap1, bp);
                mma_bf16(d[nt], ap0, ap1, br);
                mma_bf16(d[nt], ar0, ar1, bp);
            }
        }
    }
#pragma unroll
    for (int nt = 0; nt < 3; nt++) {
        int kx = nt*4 + t4;
        g_xw[(row0 + wid*16 + g    )*12 + kx] = make_float2(d[nt][0], d[nt][1]);
        g_xw[(row0 + wid*16 + g + 8)*12 + kx] = make_float2(d[nt][2], d[nt][3]);
    }
}

// ---------------- forward H-DFT ----------------
__global__ void k_fwd_h() {
    __shared__ float2 s[3072];
    __shared__ float2 tw[256];
    int bc = blockIdx.x;
    for (int t = threadIdx.x; t < 256;  t += 256) tw[t] = g_tw[t];
    for (int t = threadIdx.x; t < 3072; t += 256) s[t] = g_xw[(size_t)bc*3072 + t];
    __syncthreads();
    for (int out = threadIdx.x; out < 288; out += 256) {
        int kyi = out / 12, kx = out % 12;
        int ky  = (kyi < 12) ? kyi : (kyi + 232);
        float ar = 0.f, ai = 0.f;
        for (int y = 0; y < 256; y++) {
            float2 a = s[y*12 + kx];
            float2 w = tw[(ky*y) & 255];
            ar += a.x*w.x + a.y*w.y;
            ai += a.y*w.x - a.x*w.y;
        }
        g_xf[(size_t)bc*288 + out] = make_float2(ar, ai);
    }
}

// ---------------- mode mixing ----------------
__global__ void k_mix(int l) {
    __shared__ float2 sxf[4][64];
    int b = blockIdx.x / 72, grp = blockIdx.x % 72;
    int cell0 = grp * 4;
    {
        int c = threadIdx.x >> 6, i = threadIdx.x & 63;
        sxf[c][i] = g_xf[((size_t)b*CC + i)*288 + cell0 + c];
    }
    __syncthreads();
    int cc = threadIdx.x >> 6, o = threadIdx.x & 63;
    int cell = cell0 + cc;
    int kyi = cell / 12, kx = cell % 12;
    const float2* wp = g_wt + (((size_t)l*NKY + kyi)*12 + kx)*4096 + o;
    float ar = 0.f, ai = 0.f;
#pragma unroll 8
    for (int i = 0; i < 64; i++) {
        float2 a = sxf[cc][i];
        float2 w = wp[(size_t)i * 64];
        ar += a.x*w.x - a.y*w.y;
        ai += a.x*w.y + a.y*w.x;
    }
    g_yf[((size_t)b*CC + o)*288 + cell] = make_float2(ar, ai);
}

// ---------------- inverse H ----------------
__global__ void k_inv_h() {
    __shared__ float2 sy[288];
    __shared__ float2 tw[256];
    int bo = blockIdx.x;
    for (int t = threadIdx.x; t < 256; t += 256) tw[t] = g_tw[t];
    for (int t = threadIdx.x; t < 288; t += 256) sy[t] = g_yf[(size_t)bo*288 + t];
    __syncthreads();
    int y = threadIdx.x;
    float2 acc[12];
#pragma unroll
    for (int kx = 0; kx < 12; kx++) acc[kx] = make_float2(0.f, 0.f);
    for (int kyi = 0; kyi < 24; kyi++) {
        int ky = (kyi < 12) ? kyi : (kyi + 232);
        float2 w = tw[(ky*y) & 255];
#pragma unroll
        for (int kx = 0; kx < 12; kx++) {
            float2 a = sy[kyi*12 + kx];
            acc[kx].x += a.x*w.x - a.y*w.y;
            acc[kx].y += a.x*w.y + a.y*w.x;
        }
    }
#pragma unroll
    for (int kx = 0; kx < 12; kx++)
        g_g[((size_t)bo*256 + y)*12 + kx] = acc[kx];
}

// ---------------- fused combine: per-(b,y) block, 4 x-chunks, packed IO ----------------
#define KP 88
#define XP 68
__global__ void __launch_bounds__(256) k_combine(const float* __restrict__ pw_b, int l) {
    const unsigned* hin = (l & 1) ? g_hPB : g_hPA;
    unsigned* hpout = (l & 1) ? g_hPA : g_hPB;
    __shared__ __align__(16) unsigned sA[64*KP];
    __shared__ __align__(16) unsigned sB[64*XP];
    __shared__ __align__(16) float    sD[64*XP];
    __shared__ unsigned s_twc[256];
    __shared__ unsigned s_tws[256];
    __shared__ float  sbias[64];

    int y = blockIdx.x & 255;
    int b = blockIdx.x >> 8;
    int tid = threadIdx.x;

#pragma unroll
    for (int it = 0; it < 4; it++) {
        int t = it*256 + tid;
        int o = t >> 4, q = t & 15;
        uint4 v = *(const uint4*)(g_pwp + (size_t)l*4096 + o*64 + q*4);
        *(uint4*)&sA[o*KP + q*4] = v;
    }
#pragma unroll
    for (int it = 0; it < 3; it++) {
        int t = it*256 + tid;
        if (t < 768) {
            int o = t / 12, j = t % 12;
            float2 gv = g_g[(((size_t)b*64 + o)*256 + y)*12 + j];
            sA[o*KP + 64 + j] = split2(gv.x);
            sA[o*KP + 76 + j] = split2(gv.y);
        }
    }
    s_twc[tid & 255] = g_twc[tid & 255];
    s_tws[tid & 255] = g_tws[tid & 255];
    if (tid < 64) sbias[tid] = pw_b[l*64 + tid];

    int wid = tid >> 5, lane = tid & 31;
    int mt = wid & 3, nh = wid >> 2;
    int g = lane >> 2, t4 = lane & 3;
    const float A1 = 1.f/65536.f, A2 = 2.f/65536.f;

    uint4 pf[4];
#pragma unroll
    for (int it = 0; it < 4; it++) {
        int t = it*256 + tid;
        int i = t >> 4, q = t & 15;
        pf[it] = *(const uint4*)(hin + ((((size_t)b*64 + i)*256 + y) << 8) + q*4);
    }

#pragma unroll 1
    for (int xc = 0; xc < 4; xc++) {
        int x0 = xc << 6;
#pragma unroll
        for (int it = 0; it < 4; it++) {
            int t = it*256 + tid;
            int i = t >> 4, q = t & 15;
            *(uint4*)&sB[i*XP + q*4] = pf[it];
        }
        __syncthreads();
        if (xc < 3) {
#pragma unroll
            for (int it = 0; it < 4; it++) {
                int t = it*256 + tid;
                int i = t >> 4, q = t & 15;
                pf[it] = *(const uint4*)(hin + ((((size_t)b*64 + i)*256 + y) << 8) + x0 + 64 + q*4);
            }
        }

        float d[4][4];
#pragma unroll
        for (int nt = 0; nt < 4; nt++)
#pragma unroll
            for (int r = 0; r < 4; r++) d[nt][r] = 0.f;

#pragma unroll
        for (int kt = 0; kt < 11; kt++) {
            uint2 wA0 = *(const uint2*)&sA[(mt*16 + g    )*KP + kt*8 + 2*t4];
            uint2 wA1 = *(const uint2*)&sA[(mt*16 + g + 8)*KP + kt*8 + 2*t4];
            unsigned ap0 = prmt(wA0.x, wA0.y, 0x5410u), ar0 = prmt(wA0.x, wA0.y, 0x7632u);
            unsigned ap1 = prmt(wA1.x, wA1.y, 0x5410u), ar1 = prmt(wA1.x, wA1.y, 0x7632u);

            int er0 = (kt - 8)*8 + 2*t4;
            bool cosp = er0 < 12;
            const unsigned* tab = cosp ? s_twc : s_tws;
            int j0 = cosp ? er0 : er0 - 12;
            int j1 = j0 + 1;
            unsigned alpha = 0;
            if (kt >= 8) {
                float al0 = cosp ? ((er0 == 0) ? A1 : A2) : -A2;
                float al1 = cosp ? A2 : -A2;
                alpha = packbf2(al0, al1);
            }

#pragma unroll
            for (int nt = 0; nt < 4; nt++) {
                int xl = nh*32 + nt*8 + g;
                unsigned bp, br;
                if (kt < 8) {
                    unsigned w0 = sB[(kt*8 + 2*t4    )*XP + xl];
                    unsigned w1 = sB[(kt*8 + 2*t4 + 1)*XP + xl];
                    bp = prmt(w0, w1, 0x5410u);
                    br = prmt(w0, w1, 0x7632u);
                } else {
                    int xg = x0 + xl;
                    unsigned w0 = tab[(j0*xg) & 255];
                    unsigned w1 = tab[(j1*xg) & 255];
                    bp = mulbf2(prmt(w0, w1, 0x5410u), alpha);
                    br = mulbf2(prmt(w0, w1, 0x7632u), alpha);
                }
                mma_bf16(d[nt], ap0, ap1, bp);
                mma_bf16(d[nt], ap0, ap1, br);
                mma_bf16(d[nt], ar0, ar1, bp);
            }
        }

#pragma unroll
        for (int nt = 0; nt < 4; nt++) {
            int xl = nh*32 + nt*8 + 2*t4;
            int o0 = mt*16 + g;
            *(float2*)&sD[ o0      * XP + xl] = make_float2(d[nt][0], d[nt][1]);
            *(float2*)&sD[(o0 + 8) * XP + xl] = make_float2(d[nt][2], d[nt][3]);
        }
        __syncthreads();

#pragma unroll
        for (int it = 0; it < 4; it++) {
            int o  = it*16 + (tid >> 4);
            int x4 = tid & 15;
            float4 v = *(float4*)&sD[o*XP + x4*4];
            float bias = sbias[o];
            size_t base = ((((size_t)b*64 + o)*256 + y) << 8) + x0 + x4*4;
            if (l < 3) {
                float u0 = v.x + bias, u1 = v.y + bias, u2 = v.z + bias, u3 = v.w + bias;
                u0 = 0.5f*u0*(1.f + erff(u0*0.70710678118654752f));
                u1 = 0.5f*u1*(1.f + erff(u1*0.70710678118654752f));
                u2 = 0.5f*u2*(1.f + erff(u2*0.70710678118654752f));
                u3 = 0.5f*u3*(1.f + erff(u3*0.70710678118654752f));
                uint4 up;
                up.x = split2(u0); up.y = split2(u1); up.z = split2(u2); up.w = split2(u3);
                *(uint4*)(hpout + base) = up;
            } else {
                v.x += bias; v.y += bias; v.z += bias; v.w += bias;
                *(float4*)(g_hA + base) = v;
            }
        }
        __syncthreads();
    }
}

// ---------------- final: tensor-core fc1 + gelu + fc2 ----------------
// block = (b, y, xhalf): 128 pixels x 64 channels. fc1 GEMM M=128,N=128,K=64 bf16x3.
#define FS 132
__global__ void __launch_bounds__(256) k_final(const float* __restrict__ b1,
                        const float* __restrict__ w2, const float* __restrict__ b2,
                        float* __restrict__ out) {
    __shared__ __align__(16) unsigned sH[64*FS];   // [c][x] split-packed
    __shared__ __align__(16) unsigned sW[64*FS];   // [c][d] split-packed
    __shared__ float sb1[FCH];
    __shared__ float sw2[FCH];
    int xh = blockIdx.x & 1;
    int y  = (blockIdx.x >> 1) & 255;
    int b  = blockIdx.x >> 9;
    int tid = threadIdx.x;
    int x0 = xh << 7;

    // load h tile: 64 rows x 128 x (32 float4 per row)
#pragma unroll
    for (int it = 0; it < 8; it++) {
        int t = it*256 + tid;
        int c = t >> 5, q = t & 31;
        float4 v = *(const float4*)(g_hA + ((((size_t)b*64 + c)*256 + y) << 8) + x0 + q*4);
        sH[c*FS + q*4 + 0] = split2(v.x);
        sH[c*FS + q*4 + 1] = split2(v.y);
        sH[c*FS + q*4 + 2] = split2(v.z);
        sH[c*FS + q*4 + 3] = split2(v.w);
    }
    // load w1 packed: 64 rows x 128 d
#pragma unroll
    for (int it = 0; it < 8; it++) {
        int t = it*256 + tid;
        int c = t >> 5, q = t & 31;
        uint4 v = *(const uint4*)(g_w1p + c*128 + q*4);
        *(uint4*)&sW[c*FS + q*4] = v;
    }
    if (tid < 128) { sb1[tid] = b1[tid]; sw2[tid] = w2[tid]; }
    __syncthreads();

    int wid = tid >> 5, lane = tid & 31;
    int g = lane >> 2, t4 = lane & 3;
    // warp = m-tile: pixel rows x = wid*16 + g (+8)
    float d[16][4];
#pragma unroll
    for (int nt = 0; nt < 16; nt++)
#pragma unroll
        for (int r = 0; r < 4; r++) d[nt][r] = 0.f;

#pragma unroll
    for (int kt = 0; kt < 8; kt++) {
        int c0 = kt*8 + 2*t4;
        unsigned a0x = sH[ c0     *FS + wid*16 + g];
        unsigned a0y = sH[(c0 + 1)*FS + wid*16 + g];
        unsigned a1x = sH[ c0     *FS + wid*16 + g + 8];
        unsigned a1y = sH[(c0 + 1)*FS + wid*16 + g + 8];
        unsigned ap0 = prmt(a0x, a0y, 0x5410u), ar0 = prmt(a0x, a0y, 0x7632u);
        unsigned ap1 = prmt(a1x, a1y, 0x5410u), ar1 = prmt(a1x, a1y, 0x7632u);
#pragma unroll
        for (int nt = 0; nt < 16; nt++) {
            unsigned w0 = sW[ c0     *FS + nt*8 + g];
            unsigned w1 = sW[(c0 + 1)*FS + nt*8 + g];
            unsigned bp = prmt(w0, w1, 0x5410u);
            unsigned br = prmt(w0, w1, 0x7632u);
            mma_bf16(d[nt], ap0, ap1, bp);
            mma_bf16(d[nt], ap0, ap1, br);
            mma_bf16(d[nt], ar0, ar1, bp);
        }
    }

    // gelu + fc2 partial sums: thread owns d-cols {nt*8+2t4, +1} for pixel rows g, g+8
    float pA = 0.f, pB = 0.f;
#pragma unroll
    for (int nt = 0; nt < 16; nt++) {
        int d0 = nt*8 + 2*t4, d1 = d0 + 1;
        float bb0 = sb1[d0], bb1 = sb1[d1];
        float ww0 = sw2[d0], ww1 = sw2[d1];
        float u;
        u = d[nt][0] + bb0; u = 0.5f*u*(1.f + erff(u*0.70710678118654752f)); pA += u*ww0;
        u = d[nt][1] + bb1; u = 0.5f*u*(1.f + erff(u*0.70710678118654752f)); pA += u*ww1;
        u = d[nt][2] + bb0; u = 0.5f*u*(1.f + erff(u*0.70710678118654752f)); pB += u*ww0;
        u = d[nt][3] + bb1; u = 0.5f*u*(1.f + erff(u*0.70710678118654752f)); pB += u*ww1;
    }
    // reduce over t4 quad
    pA += __shfl_xor_sync(0xffffffffu, pA, 1);
    pA += __shfl_xor_sync(0xffffffffu, pA, 2);
    pB += __shfl_xor_sync(0xffffffffu, pB, 1);
    pB += __shfl_xor_sync(0xffffffffu, pB, 2);
    if (t4 == 0) {
        float bias2 = b2[0];
        size_t base = ((size_t)b*256 + y)*256 + x0 + wid*16 + g;
        out[base    ] = pA + bias2;
        out[base + 8] = pB + bias2;
    }
}

// ---------------- launcher ----------------
extern "C" void kernel_launch(void* const* d_in, const int* in_sizes, int n_in,
                              void* d_out, int out_size) {
    const float* x     = (const float*)d_in[0];
    const float* fc0_w = (const float*)d_in[1];
    const float* fc0_b = (const float*)d_in[2];
    const float* sc_w  = (const float*)d_in[3];
    const float* pw_w  = (const float*)d_in[4];
    const float* pw_b  = (const float*)d_in[5];
    const float* fc1_w = (const float*)d_in[6];
    const float* fc1_b = (const float*)d_in[7];
    const float* fc2_w = (const float*)d_in[8];
    const float* fc2_b = (const float*)d_in[9];
    float* out = (float*)d_out;

    k_tw<<<1, 256>>>();
    k_E<<<1, 256>>>();
    k_pws<<<64, 256>>>(pw_w);
    k_w1p<<<32, 256>>>(fc1_w);
    k_wt<<<18432, 256>>>(sc_w);
    k_lift<<<65536, 256>>>(x, fc0_w, fc0_b);
    for (int l = 0; l < 4; l++) {
        k_fwd_w<<<2048, 256>>>(l);
        k_fwd_h<<<1024, 256>>>();
        k_mix<<<1152, 256>>>(l);
        k_inv_h<<<1024, 256>>>();
        k_combine<<<4096, 256>>>(pw_b, l);
    }
    k_final<<<8192, 256>>>(fc1_b, fc2_w, fc2_b, out);
}

// round 9
// speedup vs baseline: 2.5872x; 1.0571x over previous
#include <cuda_runtime.h>
#include <cuda_bf16.h>
#include <math.h>

#define BB 16
#define HH 256
#define WW 256
#define CC 64
#define M2K 12
#define NKY 24
#define FCH 128

// ---------------- device-global scratch ----------------
__device__ float    g_hA [(size_t)BB*CC*HH*WW];   // fp32 h (final layer only)
__device__ unsigned g_hPA[(size_t)BB*CC*HH*WW];   // split-packed h ping
__device__ unsigned g_hPB[(size_t)BB*CC*HH*WW];   // split-packed h pong
__device__ float2 g_xf[(size_t)BB*CC*NKY*M2K];
__device__ float2 g_yf[(size_t)BB*CC*NKY*M2K];
__device__ float2 g_g [(size_t)BB*CC*HH*M2K];
__device__ float2 g_wt[(size_t)4*NKY*M2K*CC*CC];
__device__ float2 g_tw[256];
__device__ unsigned g_twc[256];    // split-packed cos
__device__ unsigned g_tws[256];    // split-packed sin
__device__ unsigned g_E[256*24];   // fwd-W DFT matrix split-packed
__device__ unsigned g_pwp[4*CC*CC];// split-packed pointwise weights [l][o][i]
__device__ unsigned g_w1p[CC*FCH]; // split-packed fc1 weights [c][d]

// ---------------- bf16 split-pack helpers ----------------
__device__ __forceinline__ unsigned split2(float a) {
    __nv_bfloat16 p = __float2bfloat16_rn(a);
    float pf = __bfloat162float(p);
    __nv_bfloat16 r = __float2bfloat16_rn(a - pf);
    return ((unsigned)__bfloat16_as_ushort(r) << 16) | (unsigned)__bfloat16_as_ushort(p);
}
__device__ __forceinline__ unsigned prmt(unsigned a, unsigned b, unsigned s) {
    unsigned d;
    asm("prmt.b32 %0, %1, %2, %3;" : "=r"(d) : "r"(a), "r"(b), "r"(s));
    return d;
}
__device__ __forceinline__ unsigned mulbf2(unsigned a, unsigned b) {
    unsigned d;
    asm("mul.rn.bf16x2 %0, %1, %2;" : "=r"(d) : "r"(a), "r"(b));
    return d;
}
__device__ __forceinline__ unsigned packbf2(float lo, float hi) {
    unsigned l = (unsigned)__bfloat16_as_ushort(__float2bfloat16_rn(lo));
    unsigned h = (unsigned)__bfloat16_as_ushort(__float2bfloat16_rn(hi));
    return (h << 16) | l;
}
__device__ __forceinline__ void mma_bf16(float d[4], unsigned a0, unsigned a1, unsigned b0) {
    asm volatile("mma.sync.aligned.m16n8k8.row.col.f32.bf16.bf16.f32 "
        "{%0,%1,%2,%3}, {%4,%5}, {%6}, {%0,%1,%2,%3};"
        : "+f"(d[0]), "+f"(d[1]), "+f"(d[2]), "+f"(d[3])
        : "r"(a0), "r"(a1), "r"(b0));
}
__device__ __forceinline__ void cp_async16(unsigned smem_addr, const void* gptr) {
    asm volatile("cp.async.cg.shared.global [%0], [%1], 16;"
                 :: "r"(smem_addr), "l"(gptr));
}

// ---------------- twiddle tables ----------------
__global__ void k_tw() {
    int m = threadIdx.x;
    double s, c;
    sincospi((double)m / 128.0, &s, &c);
    g_tw[m]  = make_float2((float)c, (float)s);
    g_twc[m] = split2((float)c);
    g_tws[m] = split2((float)s);
}

__global__ void k_E() {
    int x = threadIdx.x;
#pragma unroll
    for (int j = 0; j < 12; j++) {
        double s, c;
        sincospi((double)((j * x) & 255) / 128.0, &s, &c);
        g_E[x*24 + 2*j    ] = split2((float)c);
        g_E[x*24 + 2*j + 1] = split2(-(float)s);
    }
}

__global__ void k_pws(const float* __restrict__ pw) {
    int idx = blockIdx.x * 256 + threadIdx.x;
    g_pwp[idx] = split2(pw[idx]);
}
__global__ void k_w1p(const float* __restrict__ w1) {
    int idx = blockIdx.x * 256 + threadIdx.x;
    g_w1p[idx] = split2(w1[idx]);
}

// ---------------- spectral weight transpose ----------------
__global__ void k_wt(const float* __restrict__ scw) {
    size_t idx = (size_t)blockIdx.x * 256 + threadIdx.x;
    if (idx >= (size_t)4*2*CC*CC*144) return;
    size_t t = idx;
    int kx = t % 12; t /= 12;
    int ky = t % 12; t /= 12;
    int o  = t % CC; t /= CC;
    int i  = t % CC; t /= CC;
    int p  = t % 2;  t /= 2;
    int l  = (int)t;
    float re = scw[idx*2], im = scw[idx*2+1];
    int kyi = (p == 0) ? ky : (12 + ky);
    size_t dst = ((((size_t)l*NKY + kyi)*12 + kx)*CC + i)*CC + o;
    g_wt[dst] = make_float2(re, im);
}

// ---------------- lift: writes split-packed h ----------------
__global__ void k_lift(const float* __restrict__ x, const float* __restrict__ w,
                       const float* __restrict__ b) {
    size_t i4 = (size_t)blockIdx.x * 256 + threadIdx.x;
    int x4 = i4 & 63;
    int y  = (i4 >> 6) & 255;
    int c  = (i4 >> 14) & 63;
    int bb = (int)(i4 >> 20);
    float4 xv = ((const float4*)x)[((size_t)bb*256 + y)*64 + x4];
    float wc = w[c], bc = b[c];
    uint4 o;
    o.x = split2(xv.x*wc + bc); o.y = split2(xv.y*wc + bc);
    o.z = split2(xv.z*wc + bc); o.w = split2(xv.w*wc + bc);
    ((uint4*)g_hPA)[i4] = o;
}

// ---------------- fused forward: W-DFT GEMM (cp.async pipelined) + H-DFT ----------------
// block = (b,c): Xw[y,:] = h[y,0:256] x E[256x24]; then XF[kyi,kx] = sum_y Xw e^{-i ky y}
#define EST 28
#define AST 36
#define OFF_A0 7168
#define OFF_A1 16384
__global__ void __launch_bounds__(256) k_fwd(int l) {
    const unsigned* hin = (l & 1) ? g_hPB : g_hPA;
    __shared__ __align__(16) unsigned s_pool[25600];   // sE | sA0 | sA1  (100 KB)
    unsigned* sE = s_pool;
    int tid = threadIdx.x;
    int bc = blockIdx.x;
    const unsigned* hbase = hin + ((size_t)bc << 16);

    for (int t = tid; t < 256*24; t += 256)
        sE[(t/24)*EST + (t%24)] = g_E[t];

    // issue chunk 0
    {
        unsigned* sA = s_pool + OFF_A0;
#pragma unroll
        for (int it = 0; it < 8; it++) {
            int idx = it*256 + tid;
            int r = idx >> 3, q = idx & 7;
            cp_async16((unsigned)__cvta_generic_to_shared(&sA[r*AST + q*4]),
                       hbase + (r << 8) + q*4);
        }
        asm volatile("cp.async.commit_group;");
    }

    int wid = tid >> 5, lane = tid & 31, g = lane >> 2, t4 = lane & 3;
    float d[2][3][4];
#pragma unroll
    for (int mt = 0; mt < 2; mt++)
#pragma unroll
        for (int nt = 0; nt < 3; nt++)
#pragma unroll
            for (int r = 0; r < 4; r++) d[mt][nt][r] = 0.f;

#pragma unroll 1
    for (int xc = 0; xc < 8; xc++) {
        unsigned* sA = s_pool + ((xc & 1) ? OFF_A1 : OFF_A0);
        if (xc < 7) {
            unsigned* sN = s_pool + ((xc & 1) ? OFF_A0 : OFF_A1);
            int xn = (xc + 1) * 32;
#pragma unroll
            for (int it = 0; it < 8; it++) {
                int idx = it*256 + tid;
                int r = idx >> 3, q = idx & 7;
                cp_async16((unsigned)__cvta_generic_to_shared(&sN[r*AST + q*4]),
                           hbase + (r << 8) + xn + q*4);
            }
            asm volatile("cp.async.commit_group;");
            asm volatile("cp.async.wait_group 1;");
        } else {
            asm volatile("cp.async.wait_group 0;");
        }
        __syncthreads();

#pragma unroll
        for (int kk = 0; kk < 4; kk++) {
            int ko = kk*8 + 2*t4;
            int gx = xc*32 + ko;
            unsigned ap[2][2], ar[2][2];
#pragma unroll
            for (int mt = 0; mt < 2; mt++) {
                int r0 = wid*32 + mt*16 + g;
                unsigned a0x = sA[ r0     *AST + ko];
                unsigned a0y = sA[ r0     *AST + ko + 1];
                unsigned a1x = sA[(r0 + 8)*AST + ko];
                unsigned a1y = sA[(r0 + 8)*AST + ko + 1];
                ap[mt][0] = prmt(a0x, a0y, 0x5410u); ar[mt][0] = prmt(a0x, a0y, 0x7632u);
                ap[mt][1] = prmt(a1x, a1y, 0x5410u); ar[mt][1] = prmt(a1x, a1y, 0x7632u);
            }
#pragma unroll
            for (int nt = 0; nt < 3; nt++) {
                int n = nt*8 + g;
                unsigned w0 = sE[ gx     *EST + n];
                unsigned w1 = sE[(gx + 1)*EST + n];
                unsigned bp = prmt(w0, w1, 0x5410u);
                unsigned br = prmt(w0, w1, 0x7632u);
#pragma unroll
                for (int mt = 0; mt < 2; mt++) {
                    mma_bf16(d[mt][nt], ap[mt][0], ap[mt][1], bp);
                    mma_bf16(d[mt][nt], ap[mt][0], ap[mt][1], br);
                    mma_bf16(d[mt][nt], ar[mt][0], ar[mt][1], bp);
                }
            }
        }
        __syncthreads();
    }

    // phase 2: store Xw to smem (overlay on sA0), H-DFT, write g_xf
    float2* sXw = (float2*)(s_pool + OFF_A0);    // [y][kx] stride 13
    float2* stw = (float2*)(s_pool + OFF_A1);
#pragma unroll
    for (int mt = 0; mt < 2; mt++) {
        int r0 = wid*32 + mt*16 + g;
#pragma unroll
        for (int nt = 0; nt < 3; nt++) {
            int kx = nt*4 + t4;
            sXw[ r0     *13 + kx] = make_float2(d[mt][nt][0], d[mt][nt][1]);
            sXw[(r0 + 8)*13 + kx] = make_float2(d[mt][nt][2], d[mt][nt][3]);
        }
    }
    stw[tid] = g_tw[tid];
    __syncthreads();

    for (int cell = tid; cell < 288; cell += 256) {
        int kyi = cell / 12, kx = cell % 12;
        int ky  = (kyi < 12) ? kyi : (kyi + 232);
        float ar2 = 0.f, ai2 = 0.f;
        for (int y = 0; y < 256; y++) {
            float2 a = sXw[y*13 + kx];
            float2 w = stw[(ky*y) & 255];
            ar2 += a.x*w.x + a.y*w.y;
            ai2 += a.y*w.x - a.x*w.y;
        }
        g_xf[(size_t)bc*288 + cell] = make_float2(ar2, ai2);
    }
}

// ---------------- mode mixing ----------------
__global__ void k_mix(int l) {
    __shared__ float2 sxf[4][64];
    int b = blockIdx.x / 72, grp = blockIdx.x % 72;
    int cell0 = grp * 4;
    {
        int c = threadIdx.x >> 6, i = threadIdx.x & 63;
        sxf[c][i] = g_xf[((size_t)b*CC + i)*288 + cell0 + c];
    }
    __syncthreads();
    int cc = threadIdx.x >> 6, o = threadIdx.x & 63;
    int cell = cell0 + cc;
    int kyi = cell / 12, kx = cell % 12;
    const float2* wp = g_wt + (((size_t)l*NKY + kyi)*12 + kx)*4096 + o;
    float ar = 0.f, ai = 0.f;
#pragma unroll 8
    for (int i = 0; i < 64; i++) {
        float2 a = sxf[cc][i];
        float2 w = wp[(size_t)i * 64];
        ar += a.x*w.x - a.y*w.y;
        ai += a.x*w.y + a.y*w.x;
    }
    g_yf[((size_t)b*CC + o)*288 + cell] = make_float2(ar, ai);
}

// ---------------- inverse H ----------------
__global__ void k_inv_h() {
    __shared__ float2 sy[288];
    __shared__ float2 tw[256];
    int bo = blockIdx.x;
    for (int t = threadIdx.x; t < 256; t += 256) tw[t] = g_tw[t];
    for (int t = threadIdx.x; t < 288; t += 256) sy[t] = g_yf[(size_t)bo*288 + t];
    __syncthreads();
    int y = threadIdx.x;
    float2 acc[12];
#pragma unroll
    for (int kx = 0; kx < 12; kx++) acc[kx] = make_float2(0.f, 0.f);
    for (int kyi = 0; kyi < 24; kyi++) {
        int ky = (kyi < 12) ? kyi : (kyi + 232);
        float2 w = tw[(ky*y) & 255];
#pragma unroll
        for (int kx = 0; kx < 12; kx++) {
            float2 a = sy[kyi*12 + kx];
            acc[kx].x += a.x*w.x - a.y*w.y;
            acc[kx].y += a.x*w.y + a.y*w.x;
        }
    }
#pragma unroll
    for (int kx = 0; kx < 12; kx++)
        g_g[((size_t)bo*256 + y)*12 + kx] = acc[kx];
}

// ---------------- fused combine: per-(b,y) block, 4 x-chunks, packed IO ----------------
#define KP 88
#define XP 68
__global__ void __launch_bounds__(256) k_combine(const float* __restrict__ pw_b, int l) {
    const unsigned* hin = (l & 1) ? g_hPB : g_hPA;
    unsigned* hpout = (l & 1) ? g_hPA : g_hPB;
    __shared__ __align__(16) unsigned sA[64*KP];
    __shared__ __align__(16) unsigned sB[64*XP];
    __shared__ __align__(16) float    sD[64*XP];
    __shared__ unsigned s_twc[256];
    __shared__ unsigned s_tws[256];
    __shared__ float  sbias[64];

    int y = blockIdx.x & 255;
    int b = blockIdx.x >> 8;
    int tid = threadIdx.x;

#pragma unroll
    for (int it = 0; it < 4; it++) {
        int t = it*256 + tid;
        int o = t >> 4, q = t & 15;
        uint4 v = *(const uint4*)(g_pwp + (size_t)l*4096 + o*64 + q*4);
        *(uint4*)&sA[o*KP + q*4] = v;
    }
#pragma unroll
    for (int it = 0; it < 3; it++) {
        int t = it*256 + tid;
        if (t < 768) {
            int o = t / 12, j = t % 12;
            float2 gv = g_g[(((size_t)b*64 + o)*256 + y)*12 + j];
            sA[o*KP + 64 + j] = split2(gv.x);
            sA[o*KP + 76 + j] = split2(gv.y);
        }
    }
    s_twc[tid & 255] = g_twc[tid & 255];
    s_tws[tid & 255] = g_tws[tid & 255];
    if (tid < 64) sbias[tid] = pw_b[l*64 + tid];

    int wid = tid >> 5, lane = tid & 31;
    int mt = wid & 3, nh = wid >> 2;
    int g = lane >> 2, t4 = lane & 3;
    const float A1 = 1.f/65536.f, A2 = 2.f/65536.f;

    uint4 pf[4];
#pragma unroll
    for (int it = 0; it < 4; it++) {
        int t = it*256 + tid;
        int i = t >> 4, q = t & 15;
        pf[it] = *(const uint4*)(hin + ((((size_t)b*64 + i)*256 + y) << 8) + q*4);
    }

#pragma unroll 1
    for (int xc = 0; xc < 4; xc++) {
        int x0 = xc << 6;
#pragma unroll
        for (int it = 0; it < 4; it++) {
            int t = it*256 + tid;
            int i = t >> 4, q = t & 15;
            *(uint4*)&sB[i*XP + q*4] = pf[it];
        }
        __syncthreads();
        if (xc < 3) {
#pragma unroll
            for (int it = 0; it < 4; it++) {
                int t = it*256 + tid;
                int i = t >> 4, q = t & 15;
                pf[it] = *(const uint4*)(hin + ((((size_t)b*64 + i)*256 + y) << 8) + x0 + 64 + q*4);
            }
        }

        float d[4][4];
#pragma unroll
        for (int nt = 0; nt < 4; nt++)
#pragma unroll
            for (int r = 0; r < 4; r++) d[nt][r] = 0.f;

#pragma unroll
        for (int kt = 0; kt < 11; kt++) {
            uint2 wA0 = *(const uint2*)&sA[(mt*16 + g    )*KP + kt*8 + 2*t4];
            uint2 wA1 = *(const uint2*)&sA[(mt*16 + g + 8)*KP + kt*8 + 2*t4];
            unsigned ap0 = prmt(wA0.x, wA0.y, 0x5410u), ar0 = prmt(wA0.x, wA0.y, 0x7632u);
            unsigned ap1 = prmt(wA1.x, wA1.y, 0x5410u), ar1 = prmt(wA1.x, wA1.y, 0x7632u);

            int er0 = (kt - 8)*8 + 2*t4;
            bool cosp = er0 < 12;
            const unsigned* tab = cosp ? s_twc : s_tws;
            int j0 = cosp ? er0 : er0 - 12;
            int j1 = j0 + 1;
            unsigned alpha = 0;
            if (kt >= 8) {
                float al0 = cosp ? ((er0 == 0) ? A1 : A2) : -A2;
                float al1 = cosp ? A2 : -A2;
                alpha = packbf2(al0, al1);
            }

#pragma unroll
            for (int nt = 0; nt < 4; nt++) {
                int xl = nh*32 + nt*8 + g;
                unsigned bp, br;
                if (kt < 8) {
                    unsigned w0 = sB[(kt*8 + 2*t4    )*XP + xl];
                    unsigned w1 = sB[(kt*8 + 2*t4 + 1)*XP + xl];
                    bp = prmt(w0, w1, 0x5410u);
                    br = prmt(w0, w1, 0x7632u);
                } else {
                    int xg = x0 + xl;
                    unsigned w0 = tab[(j0*xg) & 255];
                    unsigned w1 = tab[(j1*xg) & 255];
                    bp = mulbf2(prmt(w0, w1, 0x5410u), alpha);
                    br = mulbf2(prmt(w0, w1, 0x7632u), alpha);
                }
                mma_bf16(d[nt], ap0, ap1, bp);
                mma_bf16(d[nt], ap0, ap1, br);
                mma_bf16(d[nt], ar0, ar1, bp);
            }
        }

#pragma unroll
        for (int nt = 0; nt < 4; nt++) {
            int xl = nh*32 + nt*8 + 2*t4;
            int o0 = mt*16 + g;
            *(float2*)&sD[ o0      * XP + xl] = make_float2(d[nt][0], d[nt][1]);
            *(float2*)&sD[(o0 + 8) * XP + xl] = make_float2(d[nt][2], d[nt][3]);
        }
        __syncthreads();

#pragma unroll
        for (int it = 0; it < 4; it++) {
            int o  = it*16 + (tid >> 4);
            int x4 = tid & 15;
            float4 v = *(float4*)&sD[o*XP + x4*4];
            float bias = sbias[o];
            size_t base = ((((size_t)b*64 + o)*256 + y) << 8) + x0 + x4*4;
            if (l < 3) {
                float u0 = v.x + bias, u1 = v.y + bias, u2 = v.z + bias, u3 = v.w + bias;
                u0 = 0.5f*u0*(1.f + erff(u0*0.70710678118654752f));
                u1 = 0.5f*u1*(1.f + erff(u1*0.70710678118654752f));
                u2 = 0.5f*u2*(1.f + erff(u2*0.70710678118654752f));
                u3 = 0.5f*u3*(1.f + erff(u3*0.70710678118654752f));
                uint4 up;
                up.x = split2(u0); up.y = split2(u1); up.z = split2(u2); up.w = split2(u3);
                *(uint4*)(hpout + base) = up;
            } else {
                v.x += bias; v.y += bias; v.z += bias; v.w += bias;
                *(float4*)(g_hA + base) = v;
            }
        }
        __syncthreads();
    }
}

// ---------------- final: tensor-core fc1 + gelu + fc2 ----------------
#define FS 132
__global__ void __launch_bounds__(256) k_final(const float* __restrict__ b1,
                        const float* __restrict__ w2, const float* __restrict__ b2,
                        float* __restrict__ out) {
    __shared__ __align__(16) unsigned sH[64*FS];   // [c][x] split-packed
    __shared__ __align__(16) unsigned sW[64*FS];   // [c][d] split-packed
    __shared__ float sb1[FCH];
    __shared__ float sw2[FCH];
    int xh = blockIdx.x & 1;
    int y  = (blockIdx.x >> 1) & 255;
    int b  = blockIdx.x >> 9;
    int tid = threadIdx.x;
    int x0 = xh << 7;

#pragma unroll
    for (int it = 0; it < 8; it++) {
        int t = it*256 + tid;
        int c = t >> 5, q = t & 31;
        float4 v = *(const float4*)(g_hA + ((((size_t)b*64 + c)*256 + y) << 8) + x0 + q*4);
        sH[c*FS + q*4 + 0] = split2(v.x);
        sH[c*FS + q*4 + 1] = split2(v.y);
        sH[c*FS + q*4 + 2] = split2(v.z);
        sH[c*FS + q*4 + 3] = split2(v.w);
    }
#pragma unroll
    for (int it = 0; it < 8; it++) {
        int t = it*256 + tid;
        int c = t >> 5, q = t & 31;
        uint4 v = *(const uint4*)(g_w1p + c*128 + q*4);
        *(uint4*)&sW[c*FS + q*4] = v;
    }
    if (tid < 128) { sb1[tid] = b1[tid]; sw2[tid] = w2[tid]; }
    __syncthreads();

    int wid = tid >> 5, lane = tid & 31;
    int g = lane >> 2, t4 = lane & 3;
    float d[16][4];
#pragma unroll
    for (int nt = 0; nt < 16; nt++)
#pragma unroll
        for (int r = 0; r < 4; r++) d[nt][r] = 0.f;

#pragma unroll
    for (int kt = 0; kt < 8; kt++) {
        int c0 = kt*8 + 2*t4;
        unsigned a0x = sH[ c0     *FS + wid*16 + g];
        unsigned a0y = sH[(c0 + 1)*FS + wid*16 + g];
        unsigned a1x = sH[ c0     *FS + wid*16 + g + 8];
        unsigned a1y = sH[(c0 + 1)*FS + wid*16 + g + 8];
        unsigned ap0 = prmt(a0x, a0y, 0x5410u), ar0 = prmt(a0x, a0y, 0x7632u);
        unsigned ap1 = prmt(a1x, a1y, 0x5410u), ar1 = prmt(a1x, a1y, 0x7632u);
#pragma unroll
        for (int nt = 0; nt < 16; nt++) {
            unsigned w0 = sW[ c0     *FS + nt*8 + g];
            unsigned w1 = sW[(c0 + 1)*FS + nt*8 + g];
            unsigned bp = prmt(w0, w1, 0x5410u);
            unsigned br = prmt(w0, w1, 0x7632u);
            mma_bf16(d[nt], ap0, ap1, bp);
            mma_bf16(d[nt], ap0, ap1, br);
            mma_bf16(d[nt], ar0, ar1, bp);
        }
    }

    float pA = 0.f, pB = 0.f;
#pragma unroll
    for (int nt = 0; nt < 16; nt++) {
        int d0 = nt*8 + 2*t4, d1 = d0 + 1;
        float bb0 = sb1[d0], bb1 = sb1[d1];
        float ww0 = sw2[d0], ww1 = sw2[d1];
        float u;
        u = d[nt][0] + bb0; u = 0.5f*u*(1.f + erff(u*0.70710678118654752f)); pA += u*ww0;
        u = d[nt][1] + bb1; u = 0.5f*u*(1.f + erff(u*0.70710678118654752f)); pA += u*ww1;
        u = d[nt][2] + bb0; u = 0.5f*u*(1.f + erff(u*0.70710678118654752f)); pB += u*ww0;
        u = d[nt][3] + bb1; u = 0.5f*u*(1.f + erff(u*0.70710678118654752f)); pB += u*ww1;
    }
    pA += __shfl_xor_sync(0xffffffffu, pA, 1);
    pA += __shfl_xor_sync(0xffffffffu, pA, 2);
    pB += __shfl_xor_sync(0xffffffffu, pB, 1);
    pB += __shfl_xor_sync(0xffffffffu, pB, 2);
    if (t4 == 0) {
        float bias2 = b2[0];
        size_t base = ((size_t)b*256 + y)*256 + x0 + wid*16 + g;
        out[base    ] = pA + bias2;
        out[base + 8] = pB + bias2;
    }
}

// ---------------- launcher ----------------
extern "C" void kernel_launch(void* const* d_in, const int* in_sizes, int n_in,
                              void* d_out, int out_size) {
    const float* x     = (const float*)d_in[0];
    const float* fc0_w = (const float*)d_in[1];
    const float* fc0_b = (const float*)d_in[2];
    const float* sc_w  = (const float*)d_in[3];
    const float* pw_w  = (const float*)d_in[4];
    const float* pw_b  = (const float*)d_in[5];
    const float* fc1_w = (const float*)d_in[6];
    const float* fc1_b = (const float*)d_in[7];
    const float* fc2_w = (const float*)d_in[8];
    const float* fc2_b = (const float*)d_in[9];
    float* out = (float*)d_out;

    k_tw<<<1, 256>>>();
    k_E<<<1, 256>>>();
    k_pws<<<64, 256>>>(pw_w);
    k_w1p<<<32, 256>>>(fc1_w);
    k_wt<<<18432, 256>>>(sc_w);
    k_lift<<<65536, 256>>>(x, fc0_w, fc0_b);
    for (int l = 0; l < 4; l++) {
        k_fwd<<<1024, 256>>>(l);
        k_mix<<<1152, 256>>>(l);
        k_inv_h<<<1024, 256>>>();
        k_combine<<<4096, 256>>>(pw_b, l);
    }
    k_final<<<8192, 256>>>(fc1_b, fc2_w, fc2_b, out);
}

// round 10
// speedup vs baseline: 2.7904x; 1.0786x over previous
#include <cuda_runtime.h>
#include <cuda_bf16.h>
#include <math.h>

#define BB 16
#define HH 256
#define WW 256
#define CC 64
#define M2K 12
#define NKY 24
#define FCH 128

// ---------------- device-global scratch ----------------
__device__ float    g_hA [(size_t)BB*CC*HH*WW];   // fp32 h (final layer only)
__device__ unsigned g_hPA[(size_t)BB*CC*HH*WW];   // split-packed h ping
__device__ unsigned g_hPB[(size_t)BB*CC*HH*WW];   // split-packed h pong
__device__ float2 g_xf[(size_t)BB*CC*NKY*M2K];
__device__ float2 g_yf[(size_t)BB*CC*NKY*M2K];
__device__ float2 g_g [(size_t)BB*CC*HH*M2K];
__device__ float2 g_wt[(size_t)4*NKY*M2K*CC*CC];
__device__ float2 g_tw[256];
__device__ unsigned g_twc[256];    // split-packed cos
__device__ unsigned g_tws[256];    // split-packed sin
__device__ unsigned g_E[256*24];   // fwd-W DFT matrix split-packed
__device__ unsigned g_pwp[4*CC*CC];// split-packed pointwise weights [l][o][i]
__device__ unsigned g_w1p[CC*FCH]; // split-packed fc1 weights [c][d]

// ---------------- bf16 split-pack helpers ----------------
__device__ __forceinline__ unsigned split2(float a) {
    __nv_bfloat16 p = __float2bfloat16_rn(a);
    float pf = __bfloat162float(p);
    __nv_bfloat16 r = __float2bfloat16_rn(a - pf);
    return ((unsigned)__bfloat16_as_ushort(r) << 16) | (unsigned)__bfloat16_as_ushort(p);
}
__device__ __forceinline__ unsigned prmt(unsigned a, unsigned b, unsigned s) {
    unsigned d;
    asm("prmt.b32 %0, %1, %2, %3;" : "=r"(d) : "r"(a), "r"(b), "r"(s));
    return d;
}
__device__ __forceinline__ unsigned mulbf2(unsigned a, unsigned b) {
    unsigned d;
    asm("mul.rn.bf16x2 %0, %1, %2;" : "=r"(d) : "r"(a), "r"(b));
    return d;
}
__device__ __forceinline__ unsigned packbf2(float lo, float hi) {
    unsigned l = (unsigned)__bfloat16_as_ushort(__float2bfloat16_rn(lo));
    unsigned h = (unsigned)__bfloat16_as_ushort(__float2bfloat16_rn(hi));
    return (h << 16) | l;
}
__device__ __forceinline__ void mma_bf16(float d[4], unsigned a0, unsigned a1, unsigned b0) {
    asm volatile("mma.sync.aligned.m16n8k8.row.col.f32.bf16.bf16.f32 "
        "{%0,%1,%2,%3}, {%4,%5}, {%6}, {%0,%1,%2,%3};"
        : "+f"(d[0]), "+f"(d[1]), "+f"(d[2]), "+f"(d[3])
        : "r"(a0), "r"(a1), "r"(b0));
}
__device__ __forceinline__ void mma16(float d[4], unsigned a0, unsigned a1,
                                      unsigned a2, unsigned a3,
                                      unsigned b0, unsigned b1) {
    asm volatile("mma.sync.aligned.m16n8k16.row.col.f32.bf16.bf16.f32 "
        "{%0,%1,%2,%3}, {%4,%5,%6,%7}, {%8,%9}, {%0,%1,%2,%3};"
        : "+f"(d[0]), "+f"(d[1]), "+f"(d[2]), "+f"(d[3])
        : "r"(a0), "r"(a1), "r"(a2), "r"(a3), "r"(b0), "r"(b1));
}
__device__ __forceinline__ void cp_async16(unsigned smem_addr, const void* gptr) {
    asm volatile("cp.async.cg.shared.global [%0], [%1], 16;"
                 :: "r"(smem_addr), "l"(gptr));
}

// ---------------- twiddle tables ----------------
__global__ void k_tw() {
    int m = threadIdx.x;
    double s, c;
    sincospi((double)m / 128.0, &s, &c);
    g_tw[m]  = make_float2((float)c, (float)s);
    g_twc[m] = split2((float)c);
    g_tws[m] = split2((float)s);
}

__global__ void k_E() {
    int x = threadIdx.x;
#pragma unroll
    for (int j = 0; j < 12; j++) {
        double s, c;
        sincospi((double)((j * x) & 255) / 128.0, &s, &c);
        g_E[x*24 + 2*j    ] = split2((float)c);
        g_E[x*24 + 2*j + 1] = split2(-(float)s);
    }
}

__global__ void k_pws(const float* __restrict__ pw) {
    int idx = blockIdx.x * 256 + threadIdx.x;
    g_pwp[idx] = split2(pw[idx]);
}
__global__ void k_w1p(const float* __restrict__ w1) {
    int idx = blockIdx.x * 256 + threadIdx.x;
    g_w1p[idx] = split2(w1[idx]);
}

// ---------------- spectral weight transpose ----------------
__global__ void k_wt(const float* __restrict__ scw) {
    size_t idx = (size_t)blockIdx.x * 256 + threadIdx.x;
    if (idx >= (size_t)4*2*CC*CC*144) return;
    size_t t = idx;
    int kx = t % 12; t /= 12;
    int ky = t % 12; t /= 12;
    int o  = t % CC; t /= CC;
    int i  = t % CC; t /= CC;
    int p  = t % 2;  t /= 2;
    int l  = (int)t;
    float re = scw[idx*2], im = scw[idx*2+1];
    int kyi = (p == 0) ? ky : (12 + ky);
    size_t dst = ((((size_t)l*NKY + kyi)*12 + kx)*CC + i)*CC + o;
    g_wt[dst] = make_float2(re, im);
}

// ---------------- lift: writes split-packed h ----------------
__global__ void k_lift(const float* __restrict__ x, const float* __restrict__ w,
                       const float* __restrict__ b) {
    size_t i4 = (size_t)blockIdx.x * 256 + threadIdx.x;
    int x4 = i4 & 63;
    int y  = (i4 >> 6) & 255;
    int c  = (i4 >> 14) & 63;
    int bb = (int)(i4 >> 20);
    float4 xv = ((const float4*)x)[((size_t)bb*256 + y)*64 + x4];
    float wc = w[c], bc = b[c];
    uint4 o;
    o.x = split2(xv.x*wc + bc); o.y = split2(xv.y*wc + bc);
    o.z = split2(xv.z*wc + bc); o.w = split2(xv.w*wc + bc);
    ((uint4*)g_hPA)[i4] = o;
}

// ---------------- fused forward: W-DFT GEMM (cp.async pipelined, k16 mma) + H-DFT ----------------
#define EST 28
#define AST 36
#define OFF_A0 7168
#define OFF_A1 16384
__global__ void __launch_bounds__(256) k_fwd(int l) {
    const unsigned* hin = (l & 1) ? g_hPB : g_hPA;
    __shared__ __align__(16) unsigned s_pool[25600];   // sE | sA0 | sA1  (100 KB)
    unsigned* sE = s_pool;
    int tid = threadIdx.x;
    int bc = blockIdx.x;
    const unsigned* hbase = hin + ((size_t)bc << 16);

    for (int t = tid; t < 256*24; t += 256)
        sE[(t/24)*EST + (t%24)] = g_E[t];

    {
        unsigned* sA = s_pool + OFF_A0;
#pragma unroll
        for (int it = 0; it < 8; it++) {
            int idx = it*256 + tid;
            int r = idx >> 3, q = idx & 7;
            cp_async16((unsigned)__cvta_generic_to_shared(&sA[r*AST + q*4]),
                       hbase + (r << 8) + q*4);
        }
        asm volatile("cp.async.commit_group;");
    }

    int wid = tid >> 5, lane = tid & 31, g = lane >> 2, t4 = lane & 3;
    float d[2][3][4];
#pragma unroll
    for (int mt = 0; mt < 2; mt++)
#pragma unroll
        for (int nt = 0; nt < 3; nt++)
#pragma unroll
            for (int r = 0; r < 4; r++) d[mt][nt][r] = 0.f;

#pragma unroll 1
    for (int xc = 0; xc < 8; xc++) {
        unsigned* sA = s_pool + ((xc & 1) ? OFF_A1 : OFF_A0);
        if (xc < 7) {
            unsigned* sN = s_pool + ((xc & 1) ? OFF_A0 : OFF_A1);
            int xn = (xc + 1) * 32;
#pragma unroll
            for (int it = 0; it < 8; it++) {
                int idx = it*256 + tid;
                int r = idx >> 3, q = idx & 7;
                cp_async16((unsigned)__cvta_generic_to_shared(&sN[r*AST + q*4]),
                           hbase + (r << 8) + xn + q*4);
            }
            asm volatile("cp.async.commit_group;");
            asm volatile("cp.async.wait_group 1;");
        } else {
            asm volatile("cp.async.wait_group 0;");
        }
        __syncthreads();

#pragma unroll
        for (int kk = 0; kk < 2; kk++) {
            int ko = kk*16 + 2*t4;
            int gx = xc*32 + ko;
            unsigned ap[2][4], ar[2][4];
#pragma unroll
            for (int mt = 0; mt < 2; mt++) {
                int r0 = wid*32 + mt*16 + g;
                uint2 L00 = *(const uint2*)&sA[ r0     *AST + ko];
                uint2 L08 = *(const uint2*)&sA[ r0     *AST + ko + 8];
                uint2 L10 = *(const uint2*)&sA[(r0 + 8)*AST + ko];
                uint2 L18 = *(const uint2*)&sA[(r0 + 8)*AST + ko + 8];
                ap[mt][0] = prmt(L00.x, L00.y, 0x5410u); ar[mt][0] = prmt(L00.x, L00.y, 0x7632u);
                ap[mt][1] = prmt(L10.x, L10.y, 0x5410u); ar[mt][1] = prmt(L10.x, L10.y, 0x7632u);
                ap[mt][2] = prmt(L08.x, L08.y, 0x5410u); ar[mt][2] = prmt(L08.x, L08.y, 0x7632u);
                ap[mt][3] = prmt(L18.x, L18.y, 0x5410u); ar[mt][3] = prmt(L18.x, L18.y, 0x7632u);
            }
#pragma unroll
            for (int nt = 0; nt < 3; nt++) {
                int n = nt*8 + g;
                unsigned w0 = sE[ gx     *EST + n];
                unsigned w1 = sE[(gx + 1)*EST + n];
                unsigned w8 = sE[(gx + 8)*EST + n];
                unsigned w9 = sE[(gx + 9)*EST + n];
                unsigned bp0 = prmt(w0, w1, 0x5410u), br0 = prmt(w0, w1, 0x7632u);
                unsigned bp1 = prmt(w8, w9, 0x5410u), br1 = prmt(w8, w9, 0x7632u);
#pragma unroll
                for (int mt = 0; mt < 2; mt++) {
                    mma16(d[mt][nt], ap[mt][0], ap[mt][1], ap[mt][2], ap[mt][3], bp0, bp1);
                    mma16(d[mt][nt], ap[mt][0], ap[mt][1], ap[mt][2], ap[mt][3], br0, br1);
                    mma16(d[mt][nt], ar[mt][0], ar[mt][1], ar[mt][2], ar[mt][3], bp0, bp1);
                }
            }
        }
        __syncthreads();
    }

    // phase 2: Xw -> smem, H-DFT, write g_xf
    float2* sXw = (float2*)(s_pool + OFF_A0);    // [y][kx] stride 13
    float2* stw = (float2*)(s_pool + OFF_A1);
#pragma unroll
    for (int mt = 0; mt < 2; mt++) {
        int r0 = wid*32 + mt*16 + g;
#pragma unroll
        for (int nt = 0; nt < 3; nt++) {
            int kx = nt*4 + t4;
            sXw[ r0     *13 + kx] = make_float2(d[mt][nt][0], d[mt][nt][1]);
            sXw[(r0 + 8)*13 + kx] = make_float2(d[mt][nt][2], d[mt][nt][3]);
        }
    }
    stw[tid] = g_tw[tid];
    __syncthreads();

    for (int cell = tid; cell < 288; cell += 256) {
        int kyi = cell / 12, kx = cell % 12;
        int ky  = (kyi < 12) ? kyi : (kyi + 232);
        float ar2 = 0.f, ai2 = 0.f;
        for (int y = 0; y < 256; y++) {
            float2 a = sXw[y*13 + kx];
            float2 w = stw[(ky*y) & 255];
            ar2 += a.x*w.x + a.y*w.y;
            ai2 += a.y*w.x - a.x*w.y;
        }
        g_xf[(size_t)bc*288 + cell] = make_float2(ar2, ai2);
    }
}

// ---------------- mode mixing ----------------
__global__ void k_mix(int l) {
    __shared__ float2 sxf[4][64];
    int b = blockIdx.x / 72, grp = blockIdx.x % 72;
    int cell0 = grp * 4;
    {
        int c = threadIdx.x >> 6, i = threadIdx.x & 63;
        sxf[c][i] = g_xf[((size_t)b*CC + i)*288 + cell0 + c];
    }
    __syncthreads();
    int cc = threadIdx.x >> 6, o = threadIdx.x & 63;
    int cell = cell0 + cc;
    int kyi = cell / 12, kx = cell % 12;
    const float2* wp = g_wt + (((size_t)l*NKY + kyi)*12 + kx)*4096 + o;
    float ar = 0.f, ai = 0.f;
#pragma unroll 8
    for (int i = 0; i < 64; i++) {
        float2 a = sxf[cc][i];
        float2 w = wp[(size_t)i * 64];
        ar += a.x*w.x - a.y*w.y;
        ai += a.x*w.y + a.y*w.x;
    }
    g_yf[((size_t)b*CC + o)*288 + cell] = make_float2(ar, ai);
}

// ---------------- inverse H ----------------
__global__ void k_inv_h() {
    __shared__ float2 sy[288];
    __shared__ float2 tw[256];
    int bo = blockIdx.x;
    for (int t = threadIdx.x; t < 256; t += 256) tw[t] = g_tw[t];
    for (int t = threadIdx.x; t < 288; t += 256) sy[t] = g_yf[(size_t)bo*288 + t];
    __syncthreads();
    int y = threadIdx.x;
    float2 acc[12];
#pragma unroll
    for (int kx = 0; kx < 12; kx++) acc[kx] = make_float2(0.f, 0.f);
    for (int kyi = 0; kyi < 24; kyi++) {
        int ky = (kyi < 12) ? kyi : (kyi + 232);
        float2 w = tw[(ky*y) & 255];
#pragma unroll
        for (int kx = 0; kx < 12; kx++) {
            float2 a = sy[kyi*12 + kx];
            acc[kx].x += a.x*w.x - a.y*w.y;
            acc[kx].y += a.x*w.y + a.y*w.x;
        }
    }
#pragma unroll
    for (int kx = 0; kx < 12; kx++)
        g_g[((size_t)bo*256 + y)*12 + kx] = acc[kx];
}

// ---------------- fused combine: per-(b,y) block, 4 x-chunks, k16 mma ----------------
#define KP 88
#define XP 68
__global__ void __launch_bounds__(256) k_combine(const float* __restrict__ pw_b, int l) {
    const unsigned* hin = (l & 1) ? g_hPB : g_hPA;
    unsigned* hpout = (l & 1) ? g_hPA : g_hPB;
    __shared__ __align__(16) unsigned sA[64*KP];
    __shared__ __align__(16) unsigned sB[64*XP];
    __shared__ __align__(16) float    sD[64*XP];
    __shared__ unsigned s_twc[256];
    __shared__ unsigned s_tws[256];
    __shared__ float  sbias[64];

    int y = blockIdx.x & 255;
    int b = blockIdx.x >> 8;
    int tid = threadIdx.x;

#pragma unroll
    for (int it = 0; it < 4; it++) {
        int t = it*256 + tid;
        int o = t >> 4, q = t & 15;
        uint4 v = *(const uint4*)(g_pwp + (size_t)l*4096 + o*64 + q*4);
        *(uint4*)&sA[o*KP + q*4] = v;
    }
#pragma unroll
    for (int it = 0; it < 3; it++) {
        int t = it*256 + tid;
        if (t < 768) {
            int o = t / 12, j = t % 12;
            float2 gv = g_g[(((size_t)b*64 + o)*256 + y)*12 + j];
            sA[o*KP + 64 + j] = split2(gv.x);
            sA[o*KP + 76 + j] = split2(gv.y);
        }
    }
    s_twc[tid & 255] = g_twc[tid & 255];
    s_tws[tid & 255] = g_tws[tid & 255];
    if (tid < 64) sbias[tid] = pw_b[l*64 + tid];

    int wid = tid >> 5, lane = tid & 31;
    int mt = wid & 3, nh = wid >> 2;
    int g = lane >> 2, t4 = lane & 3;
    const float A1 = 1.f/65536.f, A2 = 2.f/65536.f;

    uint4 pf[4];
#pragma unroll
    for (int it = 0; it < 4; it++) {
        int t = it*256 + tid;
        int i = t >> 4, q = t & 15;
        pf[it] = *(const uint4*)(hin + ((((size_t)b*64 + i)*256 + y) << 8) + q*4);
    }

#pragma unroll 1
    for (int xc = 0; xc < 4; xc++) {
        int x0 = xc << 6;
#pragma unroll
        for (int it = 0; it < 4; it++) {
            int t = it*256 + tid;
            int i = t >> 4, q = t & 15;
            *(uint4*)&sB[i*XP + q*4] = pf[it];
        }
        __syncthreads();
        if (xc < 3) {
#pragma unroll
            for (int it = 0; it < 4; it++) {
                int t = it*256 + tid;
                int i = t >> 4, q = t & 15;
                pf[it] = *(const uint4*)(hin + ((((size_t)b*64 + i)*256 + y) << 8) + x0 + 64 + q*4);
            }
        }

        float d[4][4];
#pragma unroll
        for (int nt = 0; nt < 4; nt++)
#pragma unroll
            for (int r = 0; r < 4; r++) d[nt][r] = 0.f;

        // K=64 pointwise weights: 4 k16 tiles
#pragma unroll
        for (int kt = 0; kt < 4; kt++) {
            int kb = kt*16 + 2*t4;
            uint2 A00 = *(const uint2*)&sA[(mt*16 + g    )*KP + kb];
            uint2 A08 = *(const uint2*)&sA[(mt*16 + g    )*KP + kb + 8];
            uint2 A10 = *(const uint2*)&sA[(mt*16 + g + 8)*KP + kb];
            uint2 A18 = *(const uint2*)&sA[(mt*16 + g + 8)*KP + kb + 8];
            unsigned ap0 = prmt(A00.x, A00.y, 0x5410u), ar0 = prmt(A00.x, A00.y, 0x7632u);
            unsigned ap1 = prmt(A10.x, A10.y, 0x5410u), ar1 = prmt(A10.x, A10.y, 0x7632u);
            unsigned ap2 = prmt(A08.x, A08.y, 0x5410u), ar2 = prmt(A08.x, A08.y, 0x7632u);
            unsigned ap3 = prmt(A18.x, A18.y, 0x5410u), ar3 = prmt(A18.x, A18.y, 0x7632u);
#pragma unroll
            for (int nt = 0; nt < 4; nt++) {
                int xl = nh*32 + nt*8 + g;
                unsigned w00 = sB[(kb    )*XP + xl];
                unsigned w01 = sB[(kb + 1)*XP + xl];
                unsigned w08 = sB[(kb + 8)*XP + xl];
                unsigned w09 = sB[(kb + 9)*XP + xl];
                unsigned bp0 = prmt(w00, w01, 0x5410u), br0 = prmt(w00, w01, 0x7632u);
                unsigned bp1 = prmt(w08, w09, 0x5410u), br1 = prmt(w08, w09, 0x7632u);
                mma16(d[nt], ap0, ap1, ap2, ap3, bp0, bp1);
                mma16(d[nt], ap0, ap1, ap2, ap3, br0, br1);
                mma16(d[nt], ar0, ar1, ar2, ar3, bp0, bp1);
            }
        }

        // spectral K=24: one k16 tile (e 0..15) + one k8 tile (e 16..23)
        {
            int e0 = 2*t4;           // cos rows e0, e0+1
            int e1 = 2*t4 + 8;       // cos if <12 else sin rows e1-12, e1-11
            uint2 A00 = *(const uint2*)&sA[(mt*16 + g    )*KP + 64 + e0];
            uint2 A08 = *(const uint2*)&sA[(mt*16 + g    )*KP + 64 + e0 + 8];
            uint2 A10 = *(const uint2*)&sA[(mt*16 + g + 8)*KP + 64 + e0];
            uint2 A18 = *(const uint2*)&sA[(mt*16 + g + 8)*KP + 64 + e0 + 8];
            unsigned ap0 = prmt(A00.x, A00.y, 0x5410u), ar0 = prmt(A00.x, A00.y, 0x7632u);
            unsigned ap1 = prmt(A10.x, A10.y, 0x5410u), ar1 = prmt(A10.x, A10.y, 0x7632u);
            unsigned ap2 = prmt(A08.x, A08.y, 0x5410u), ar2 = prmt(A08.x, A08.y, 0x7632u);
            unsigned ap3 = prmt(A18.x, A18.y, 0x5410u), ar3 = prmt(A18.x, A18.y, 0x7632u);
            unsigned alpha0 = packbf2((e0 == 0) ? A1 : A2, A2);
            bool sin1 = (e1 >= 12);
            const unsigned* tab1 = sin1 ? s_tws : s_twc;
            int j1 = sin1 ? (e1 - 12) : e1;
            unsigned alpha1 = sin1 ? packbf2(-A2, -A2) : packbf2(A2, A2);
#pragma unroll
            for (int nt = 0; nt < 4; nt++) {
                int xl = nh*32 + nt*8 + g;
                int xg = x0 + xl;
                unsigned w00 = s_twc[( e0     *xg) & 255];
                unsigned w01 = s_twc[((e0 + 1)*xg) & 255];
                unsigned w10 = tab1[( j1     *xg) & 255];
                unsigned w11 = tab1[((j1 + 1)*xg) & 255];
                unsigned bp0 = mulbf2(prmt(w00, w01, 0x5410u), alpha0);
                unsigned br0 = mulbf2(prmt(w00, w01, 0x7632u), alpha0);
                unsigned bp1 = mulbf2(prmt(w10, w11, 0x5410u), alpha1);
                unsigned br1 = mulbf2(prmt(w10, w11, 0x7632u), alpha1);
                mma16(d[nt], ap0, ap1, ap2, ap3, bp0, bp1);
                mma16(d[nt], ap0, ap1, ap2, ap3, br0, br1);
                mma16(d[nt], ar0, ar1, ar2, ar3, bp0, bp1);
            }
        }
        {
            // k8 tail: e 16..23 -> sin rows j = 4+2t4, +1
            uint2 A0 = *(const uint2*)&sA[(mt*16 + g    )*KP + 80 + 2*t4];
            uint2 A1r = *(const uint2*)&sA[(mt*16 + g + 8)*KP + 80 + 2*t4];
            unsigned ap0 = prmt(A0.x,  A0.y,  0x5410u), ar0 = prmt(A0.x,  A0.y,  0x7632u);
            unsigned ap1 = prmt(A1r.x, A1r.y, 0x5410u), ar1 = prmt(A1r.x, A1r.y, 0x7632u);
            int j = 4 + 2*t4;
            unsigned alpha = packbf2(-A2, -A2);
#pragma unroll
            for (int nt = 0; nt < 4; nt++) {
                int xl = nh*32 + nt*8 + g;
                int xg = x0 + xl;
                unsigned w0 = s_tws[( j     *xg) & 255];
                unsigned w1 = s_tws[((j + 1)*xg) & 255];
                unsigned bp = mulbf2(prmt(w0, w1, 0x5410u), alpha);
                unsigned br = mulbf2(prmt(w0, w1, 0x7632u), alpha);
                mma_bf16(d[nt], ap0, ap1, bp);
                mma_bf16(d[nt], ap0, ap1, br);
                mma_bf16(d[nt], ar0, ar1, bp);
            }
        }

#pragma unroll
        for (int nt = 0; nt < 4; nt++) {
            int xl = nh*32 + nt*8 + 2*t4;
            int o0 = mt*16 + g;
            *(float2*)&sD[ o0      * XP + xl] = make_float2(d[nt][0], d[nt][1]);
            *(float2*)&sD[(o0 + 8) * XP + xl] = make_float2(d[nt][2], d[nt][3]);
        }
        __syncthreads();

#pragma unroll
        for (int it = 0; it < 4; it++) {
            int o  = it*16 + (tid >> 4);
            int x4 = tid & 15;
            float4 v = *(float4*)&sD[o*XP + x4*4];
            float bias = sbias[o];
            size_t base = ((((size_t)b*64 + o)*256 + y) << 8) + x0 + x4*4;
            if (l < 3) {
                float u0 = v.x + bias, u1 = v.y + bias, u2 = v.z + bias, u3 = v.w + bias;
                u0 = 0.5f*u0*(1.f + erff(u0*0.70710678118654752f));
                u1 = 0.5f*u1*(1.f + erff(u1*0.70710678118654752f));
                u2 = 0.5f*u2*(1.f + erff(u2*0.70710678118654752f));
                u3 = 0.5f*u3*(1.f + erff(u3*0.70710678118654752f));
                uint4 up;
                up.x = split2(u0); up.y = split2(u1); up.z = split2(u2); up.w = split2(u3);
                *(uint4*)(hpout + base) = up;
            } else {
                v.x += bias; v.y += bias; v.z += bias; v.w += bias;
                *(float4*)(g_hA + base) = v;
            }
        }
        __syncthreads();
    }
}

// ---------------- final: tensor-core fc1 (k16) + gelu + fc2 ----------------
#define FS 132
__global__ void __launch_bounds__(256) k_final(const float* __restrict__ b1,
                        const float* __restrict__ w2, const float* __restrict__ b2,
                        float* __restrict__ out) {
    __shared__ __align__(16) unsigned sH[64*FS];   // [c][x] split-packed
    __shared__ __align__(16) unsigned sW[64*FS];   // [c][d] split-packed
    __shared__ float sb1[FCH];
    __shared__ float sw2[FCH];
    int xh = blockIdx.x & 1;
    int y  = (blockIdx.x >> 1) & 255;
    int b  = blockIdx.x >> 9;
    int tid = threadIdx.x;
    int x0 = xh << 7;

#pragma unroll
    for (int it = 0; it < 8; it++) {
        int t = it*256 + tid;
        int c = t >> 5, q = t & 31;
        float4 v = *(const float4*)(g_hA + ((((size_t)b*64 + c)*256 + y) << 8) + x0 + q*4);
        sH[c*FS + q*4 + 0] = split2(v.x);
        sH[c*FS + q*4 + 1] = split2(v.y);
        sH[c*FS + q*4 + 2] = split2(v.z);
        sH[c*FS + q*4 + 3] = split2(v.w);
    }
#pragma unroll
    for (int it = 0; it < 8; it++) {
        int t = it*256 + tid;
        int c = t >> 5, q = t & 31;
        uint4 v = *(const uint4*)(g_w1p + c*128 + q*4);
        *(uint4*)&sW[c*FS + q*4] = v;
    }
    if (tid < 128) { sb1[tid] = b1[tid]; sw2[tid] = w2[tid]; }
    __syncthreads();

    int wid = tid >> 5, lane = tid & 31;
    int g = lane >> 2, t4 = lane & 3;
    float d[16][4];
#pragma unroll
    for (int nt = 0; nt < 16; nt++)
#pragma unroll
        for (int r = 0; r < 4; r++) d[nt][r] = 0.f;

#pragma unroll
    for (int kt = 0; kt < 4; kt++) {
        int c0 = kt*16 + 2*t4;
        int X0 = wid*16 + g;
        unsigned a00 = sH[ c0     *FS + X0], a01 = sH[(c0 + 1)*FS + X0];
        unsigned a08 = sH[(c0 + 8)*FS + X0], a09 = sH[(c0 + 9)*FS + X0];
        unsigned a10 = sH[ c0     *FS + X0 + 8], a11 = sH[(c0 + 1)*FS + X0 + 8];
        unsigned a18 = sH[(c0 + 8)*FS + X0 + 8], a19 = sH[(c0 + 9)*FS + X0 + 8];
        unsigned ap0 = prmt(a00, a01, 0x5410u), ar0 = prmt(a00, a01, 0x7632u);
        unsigned ap1 = prmt(a10, a11, 0x5410u), ar1 = prmt(a10, a11, 0x7632u);
        unsigned ap2 = prmt(a08, a09, 0x5410u), ar2 = prmt(a08, a09, 0x7632u);
        unsigned ap3 = prmt(a18, a19, 0x5410u), ar3 = prmt(a18, a19, 0x7632u);
#pragma unroll
        for (int nt = 0; nt < 16; nt++) {
            int n = nt*8 + g;
            unsigned w00 = sW[ c0     *FS + n], w01 = sW[(c0 + 1)*FS + n];
            unsigned w08 = sW[(c0 + 8)*FS + n], w09 = sW[(c0 + 9)*FS + n];
            unsigned bp0 = prmt(w00, w01, 0x5410u), br0 = prmt(w00, w01, 0x7632u);
            unsigned bp1 = prmt(w08, w09, 0x5410u), br1 = prmt(w08, w09, 0x7632u);
            mma16(d[nt], ap0, ap1, ap2, ap3, bp0, bp1);
            mma16(d[nt], ap0, ap1, ap2, ap3, br0, br1);
            mma16(d[nt], ar0, ar1, ar2, ar3, bp0, bp1);
        }
    }

    float pA = 0.f, pB = 0.f;
#pragma unroll
    for (int nt = 0; nt < 16; nt++) {
        int d0 = nt*8 + 2*t4, d1 = d0 + 1;
        float bb0 = sb1[d0], bb1 = sb1[d1];
        float ww0 = sw2[d0], ww1 = sw2[d1];
        float u;
        u = d[nt][0] + bb0; u = 0.5f*u*(1.f + erff(u*0.70710678118654752f)); pA += u*ww0;
        u = d[nt][1] + bb1; u = 0.5f*u*(1.f + erff(u*0.70710678118654752f)); pA += u*ww1;
        u = d[nt][2] + bb0; u = 0.5f*u*(1.f + erff(u*0.70710678118654752f)); pB += u*ww0;
        u = d[nt][3] + bb1; u = 0.5f*u*(1.f + erff(u*0.70710678118654752f)); pB += u*ww1;
    }
    pA += __shfl_xor_sync(0xffffffffu, pA, 1);
    pA += __shfl_xor_sync(0xffffffffu, pA, 2);
    pB += __shfl_xor_sync(0xffffffffu, pB, 1);
    pB += __shfl_xor_sync(0xffffffffu, pB, 2);
    if (t4 == 0) {
        float bias2 = b2[0];
        size_t base = ((size_t)b*256 + y)*256 + x0 + wid*16 + g;
        out[base    ] = pA + bias2;
        out[base + 8] = pB + bias2;
    }
}

// ---------------- launcher ----------------
extern "C" void kernel_launch(void* const* d_in, const int* in_sizes, int n_in,
                              void* d_out, int out_size) {
    const float* x     = (const float*)d_in[0];
    const float* fc0_w = (const float*)d_in[1];
    const float* fc0_b = (const float*)d_in[2];
    const float* sc_w  = (const float*)d_in[3];
    const float* pw_w  = (const float*)d_in[4];
    const float* pw_b  = (const float*)d_in[5];
    const float* fc1_w = (const float*)d_in[6];
    const float* fc1_b = (const float*)d_in[7];
    const float* fc2_w = (const float*)d_in[8];
    const float* fc2_b = (const float*)d_in[9];
    float* out = (float*)d_out;

    // ordered so launch #4 (the one ncu samples) is k_fwd
    k_E<<<1, 256>>>();
    k_tw<<<1, 256>>>();
    k_lift<<<65536, 256>>>(x, fc0_w, fc0_b);
    k_fwd<<<1024, 256>>>(0);
    k_wt<<<18432, 256>>>(sc_w);
    k_pws<<<64, 256>>>(pw_w);
    k_w1p<<<32, 256>>>(fc1_w);
    k_mix<<<1152, 256>>>(0);
    k_inv_h<<<1024, 256>>>();
    k_combine<<<4096, 256>>>(pw_b, 0);
    for (int l = 1; l < 4; l++) {
        k_fwd<<<1024, 256>>>(l);
        k_mix<<<1152, 256>>>(l);
        k_inv_h<<<1024, 256>>>();
        k_combine<<<4096, 256>>>(pw_b, l);
    }
    k_final<<<8192, 256>>>(fc1_b, fc2_w, fc2_b, out);
}